// round 14
// baseline (speedup 1.0000x reference)
#include <cuda_runtime.h>
#include <cuda_fp16.h>
#include <cstdint>

// Problem constants
#define Bn  8
#define Cc  512
#define Ln  4096
#define Hh  8
#define Dh  64
#define NSPLIT 16

// ---------------------------------------------------------------------------
// Scratch
// ---------------------------------------------------------------------------
__device__ float g_scratch[135266304];
__device__ __half g_hf[102760448];

// half-element offsets into g_hf
#define OFF_Z1C  0ull
#define OFF_Z2C  16777216ull
#define OFF_ATTC 33554432ull
#define OFF_ZC   50331648ull
#define OFF_HC   67108864ull
#define OFF_WQ   100663296ull
#define OFF_WK   100925440ull
#define OFF_WV   101187584ull
#define OFF_WR   101449728ull
#define OFF_W1   101711872ull
#define OFF_W2   102236160ull

// ---------------------------------------------------------------------------
// Helpers
// ---------------------------------------------------------------------------
__device__ __forceinline__ uint32_t smem_u32(const void* p) {
    uint32_t a;
    asm("{ .reg .u64 t; cvta.to.shared.u64 t, %1; cvt.u32.u64 %0, t; }"
        : "=r"(a) : "l"(p));
    return a;
}
__device__ __host__ __forceinline__ uint32_t swz128(uint32_t off) {
    return off ^ ((off >> 3) & 0x70);
}
__device__ __forceinline__ void cpasync16(uint32_t d, const void* s) {
    asm volatile("cp.async.cg.shared.global [%0], [%1], 16;" :: "r"(d), "l"(s));
}
#define CP_COMMIT() asm volatile("cp.async.commit_group;" ::: "memory")
#define CP_WAIT(N)  asm volatile("cp.async.wait_group " #N ";" ::: "memory")

#define LDSM4(R, ADDR) \
    asm volatile("ldmatrix.sync.aligned.m8n8.x4.shared.b16 {%0,%1,%2,%3}, [%4];" \
        : "=r"((R)[0]), "=r"((R)[1]), "=r"((R)[2]), "=r"((R)[3]) : "r"(ADDR))

#define MMA16816(C, A, Bv) \
    asm volatile("mma.sync.aligned.m16n8k16.row.col.f32.f16.f16.f32 " \
        "{%0,%1,%2,%3}, {%4,%5,%6,%7}, {%8,%9}, {%0,%1,%2,%3};" \
        : "+f"((C)[0]), "+f"((C)[1]), "+f"((C)[2]), "+f"((C)[3]) \
        : "r"((A)[0]), "r"((A)[1]), "r"((A)[2]), "r"((A)[3]), \
          "r"((Bv)[0]), "r"((Bv)[1]))

__device__ __forceinline__ uint32_t pack2h(float a, float b) {
    __half2 h = __floats2half2_rn(a, b);
    return *(uint32_t*)&h;
}

#define STG 32768u
#define GEMM_SMEM 98304   // 3 stages

// ---------------------------------------------------------------------------
// Convert ALL weights in one launch. grid (16, 8, 6)
// ---------------------------------------------------------------------------
__global__ __launch_bounds__(256) void conv_w_all(
    const float* __restrict__ Wq, const float* __restrict__ Wk,
    const float* __restrict__ Wv, const float* __restrict__ Wr,
    const float* __restrict__ W1, const float* __restrict__ W2,
    __half* __restrict__ hf)
{
    int widx = blockIdx.z;
    const float* src;
    __half* dstb;
    int K, MT;
    switch (widx) {
        case 0: src = Wq; dstb = hf + OFF_WQ; K = 512;  MT = 4; break;
        case 1: src = Wk; dstb = hf + OFF_WK; K = 512;  MT = 4; break;
        case 2: src = Wv; dstb = hf + OFF_WV; K = 512;  MT = 4; break;
        case 3: src = Wr; dstb = hf + OFF_WR; K = 512;  MT = 4; break;
        case 4: src = W1; dstb = hf + OFF_W1; K = 512;  MT = 8; break;
        default: src = W2; dstb = hf + OFF_W2; K = 1024; MT = 4; break;
    }
    int NC = K >> 6;
    int kc = blockIdx.x, mt = blockIdx.y;
    if (kc >= NC || mt >= MT) return;
    char* db = (char*)(dstb + ((size_t)(mt * NC + kc)) * 8192);
    const float* sb = src + ((size_t)mt * 128) * K + kc * 64;
    for (int it = 0; it < 4; it++) {
        int u = threadIdx.x + 256 * it;
        int r = u >> 3, g = u & 7;
        float x0[8];
        #pragma unroll
        for (int q = 0; q < 2; q++) {
            float4 v = *(const float4*)(sb + (size_t)r * K + g * 8 + q * 4);
            x0[q*4+0]=v.x; x0[q*4+1]=v.y; x0[q*4+2]=v.z; x0[q*4+3]=v.w;
        }
        uint4 w;
        w.x = pack2h(x0[0], x0[1]);
        w.y = pack2h(x0[2], x0[3]);
        w.z = pack2h(x0[4], x0[5]);
        w.w = pack2h(x0[6], x0[7]);
        uint32_t sw = swz128((uint32_t)r * 128 + g * 16);
        *(uint4*)(db + sw) = w;
    }
}

// ---------------------------------------------------------------------------
// Convert+transpose z1 and z2 in one launch: grid (8, 16, 16)
// ---------------------------------------------------------------------------
__global__ __launch_bounds__(256) void conv_x2(
    const float* __restrict__ src1, const float* __restrict__ src2,
    __half* __restrict__ dst1, __half* __restrict__ dst2)
{
    const int K = 512;
    int kc = blockIdx.x, lt = blockIdx.y;
    int b = blockIdx.z & 7;
    const float* src = (blockIdx.z < 8) ? src1 : src2;
    __half* dstb = (blockIdx.z < 8) ? dst1 : dst2;
    int NC = K >> 6;
    __shared__ float sm[32][264];
    const float* sb = src + ((size_t)b * K + kc * 64) * Ln + (size_t)lt * 256;
    char* db = (char*)(dstb + (((size_t)b * 16 + lt) * NC + kc) * 16384);
    int t = threadIdx.x;
    for (int p = 0; p < 2; p++) {
        __syncthreads();
        #pragma unroll
        for (int i = 0; i < 8; i++) {
            int u = t + 256 * i;
            int kr = u >> 6;
            int lc = u & 63;
            float4 v = *(const float4*)(sb + ((size_t)(p * 32 + kr)) * Ln + lc * 4);
            sm[kr][lc*4+0]=v.x; sm[kr][lc*4+1]=v.y; sm[kr][lc*4+2]=v.z; sm[kr][lc*4+3]=v.w;
        }
        __syncthreads();
        #pragma unroll
        for (int g = 0; g < 4; g++) {
            float x0[8];
            #pragma unroll
            for (int j = 0; j < 8; j++) x0[j] = sm[g*8+j][t];
            uint4 w;
            w.x = pack2h(x0[0], x0[1]);
            w.y = pack2h(x0[2], x0[3]);
            w.z = pack2h(x0[4], x0[5]);
            w.w = pack2h(x0[6], x0[7]);
            uint32_t sw = swz128((uint32_t)t * 128 + (p * 32 + g * 8) * 2);
            *(uint4*)(db + sw) = w;
        }
    }
}

// ---------------------------------------------------------------------------
// Shared GEMM mainloop (256 threads, 8 warps 64x32, 128x128 tile, 3 stages)
// ---------------------------------------------------------------------------
#define GEMM_PROLOGUE() \
    uint32_t sbase = smem_u32(smem); \
    int tid = threadIdx.x, wid = tid >> 5, lane = tid & 31; \
    int wm = wid >> 2, wn = wid & 3; \
    int sub = lane >> 3, r = lane & 7; \
    uint32_t aRow[4], aMask[4]; \
    int kaddA = (sub >> 1) * 16; \
    _Pragma("unroll") \
    for (int i = 0; i < 4; i++) { \
        uint32_t row = wm * 64 + i * 16 + (sub & 1) * 8 + r; \
        aRow[i] = row * 128; \
        aMask[i] = (aRow[i] >> 3) & 0x70; \
    } \
    uint32_t bRow[2], bMask[2]; \
    int kaddB = (sub & 1) * 16; \
    _Pragma("unroll") \
    for (int j = 0; j < 2; j++) { \
        uint32_t row = wn * 32 + j * 16 + (sub >> 1) * 8 + r; \
        bRow[j] = row * 128; \
        bMask[j] = (bRow[j] >> 3) & 0x70; \
    } \
    float acc[4][4][4]; \
    _Pragma("unroll") \
    for (int i = 0; i < 4; i++) \
        _Pragma("unroll") \
        for (int j = 0; j < 4; j++) \
            _Pragma("unroll") \
            for (int q = 0; q < 4; q++) acc[i][j][q] = 0.f;

#define GEMM_LOAD_STAGE(kc, s) do { \
    uint32_t S = sbase + (uint32_t)(s) * STG; \
    const char* ah = Abase + (size_t)(kc) * 16384; \
    const char* bh = Bbase + (size_t)(kc) * 32768; \
    _Pragma("unroll") \
    for (int q = 0; q < 4; q++) { \
        uint32_t off = (uint32_t)tid * 64 + q * 16; \
        cpasync16(S + off,         ah + off); \
        cpasync16(S + 16384 + off, bh + off); \
    } \
} while (0)

#define GEMM_MAINLOOP(NC) \
    GEMM_LOAD_STAGE(0, 0); CP_COMMIT(); \
    if ((NC) > 1) { GEMM_LOAD_STAGE(1, 1); CP_COMMIT(); } \
    int sc = 0; \
    for (int c = 0; c < (NC); c++) { \
        CP_WAIT(1); \
        __syncthreads(); \
        if (c + 2 < (NC)) { \
            int s2 = sc + 2; if (s2 >= 3) s2 -= 3; \
            GEMM_LOAD_STAGE(c + 2, s2); CP_COMMIT(); \
        } \
        uint32_t S = sbase + (uint32_t)sc * STG; \
        _Pragma("unroll") \
        for (int kk = 0; kk < 4; kk++) { \
            int kb = kk * 32; \
            uint32_t aa[16], bb[8]; \
            _Pragma("unroll") \
            for (int i = 0; i < 4; i++) \
                LDSM4(&aa[i * 4], S + aRow[i] + (uint32_t)((kaddA + kb) ^ aMask[i])); \
            _Pragma("unroll") \
            for (int j = 0; j < 2; j++) \
                LDSM4(&bb[j * 4], S + 16384 + bRow[j] + (uint32_t)((kaddB + kb) ^ bMask[j])); \
            _Pragma("unroll") \
            for (int mi = 0; mi < 4; mi++) \
                _Pragma("unroll") \
                for (int nj = 0; nj < 4; nj++) \
                    MMA16816(acc[mi][nj], &aa[mi * 4], &bb[nj * 2]); \
        } \
        sc++; if (sc == 3) sc = 0; \
    }

// ---------------------------------------------------------------------------
// Merged Q/K/V projection GEMM: grid (4, 32, 24); z>>3 selects {Q,K,V}.
// All outputs fp16 flat [B, C, L].
// ---------------------------------------------------------------------------
__global__ __launch_bounds__(256, 2) void gemm_qkv(
    const __half* __restrict__ hf,
    const float* __restrict__ bq, const float* __restrict__ bk,
    const float* __restrict__ bv,
    __half* __restrict__ qh, __half* __restrict__ kh, __half* __restrict__ vh)
{
    extern __shared__ __align__(1024) char smem[];
    const int NC = 8;
    int mt = blockIdx.x, lt = blockIdx.y;
    int which = blockIdx.z >> 3, b = blockIdx.z & 7;

    const __half* Wc = (which == 0) ? hf + OFF_WQ : (which == 1) ? hf + OFF_WK : hf + OFF_WV;
    const float* bias = (which == 0) ? bq : (which == 1) ? bk : bv;
    const __half* Xc = (which == 0) ? hf + OFF_Z1C : hf + OFF_Z2C;
    __half* Out = (which == 0) ? qh : (which == 1) ? kh : vh;

    const char* Abase = (const char*)Wc + ((size_t)mt * NC) * 16384;
    int lt256 = lt >> 1, half = lt & 1;
    const char* Bbase = (const char*)Xc + (((size_t)b * 16 + lt256) * NC) * 32768
                        + (size_t)half * 16384;

    GEMM_PROLOGUE();
    GEMM_MAINLOOP(NC);

    int g = lane >> 2, tg = lane & 3;
    #pragma unroll
    for (int mi = 0; mi < 4; mi++) {
        #pragma unroll
        for (int h2 = 0; h2 < 2; h2++) {
            int m = mt * 128 + wm * 64 + mi * 16 + h2 * 8 + g;
            float bi = bias[m];
            size_t rowoff = ((size_t)b * 512 + m) * Ln + (size_t)lt * 128 + wn * 32;
            #pragma unroll
            for (int nj = 0; nj < 4; nj++) {
                int col = nj * 8 + 2 * tg;
                float v0 = acc[mi][nj][h2 * 2 + 0] + bi;
                float v1 = acc[mi][nj][h2 * 2 + 1] + bi;
                *(__half2*)(Out + rowoff + col) = __floats2half2_rn(v0, v1);
            }
        }
    }
}

// ---------------------------------------------------------------------------
// General GEMM. outmode 0: fp32 Out (+Res)(+ELU). outmode 1: fp16 tiled Outh.
// outmode 2: fp16 flat Outh (+Res fp32)(+ELU).
// ---------------------------------------------------------------------------
__global__ __launch_bounds__(256, 2) void gemm_wm(
    const __half* __restrict__ Wc, const float* __restrict__ bias,
    const __half* __restrict__ Xc, float* __restrict__ Out,
    __half* __restrict__ Outh,
    const float* __restrict__ Res, int M, int K, int act, int outmode)
{
    extern __shared__ __align__(1024) char smem[];
    const int NC = K >> 6;
    int mt = blockIdx.x, lt = blockIdx.y, b = blockIdx.z;

    const char* Abase = (const char*)Wc + ((size_t)mt * NC) * 16384;
    int lt256 = lt >> 1, half = lt & 1;
    const char* Bbase = (const char*)Xc + (((size_t)b * 16 + lt256) * NC) * 32768
                        + (size_t)half * 16384;

    GEMM_PROLOGUE();
    GEMM_MAINLOOP(NC);

    int g = lane >> 2, tg = lane & 3;

    if (outmode == 0) {
        #pragma unroll
        for (int mi = 0; mi < 4; mi++) {
            #pragma unroll
            for (int h2 = 0; h2 < 2; h2++) {
                int m = mt * 128 + wm * 64 + mi * 16 + h2 * 8 + g;
                float bi = bias[m];
                size_t rowoff = ((size_t)b * M + m) * Ln + (size_t)lt * 128 + wn * 32;
                #pragma unroll
                for (int nj = 0; nj < 4; nj++) {
                    int col = nj * 8 + 2 * tg;
                    float v0 = acc[mi][nj][h2 * 2 + 0] + bi;
                    float v1 = acc[mi][nj][h2 * 2 + 1] + bi;
                    if (Res) {
                        float2 r2 = *(const float2*)(Res + rowoff + col);
                        v0 += r2.x; v1 += r2.y;
                    }
                    if (act) {
                        v0 = v0 > 0.f ? v0 : expm1f(v0);
                        v1 = v1 > 0.f ? v1 : expm1f(v1);
                    }
                    *(float2*)(Out + rowoff + col) = make_float2(v0, v1);
                }
            }
        }
    } else if (outmode == 2) {
        #pragma unroll
        for (int mi = 0; mi < 4; mi++) {
            #pragma unroll
            for (int h2 = 0; h2 < 2; h2++) {
                int m = mt * 128 + wm * 64 + mi * 16 + h2 * 8 + g;
                float bi = bias[m];
                size_t rowoff = ((size_t)b * M + m) * Ln + (size_t)lt * 128 + wn * 32;
                #pragma unroll
                for (int nj = 0; nj < 4; nj++) {
                    int col = nj * 8 + 2 * tg;
                    float v0 = acc[mi][nj][h2 * 2 + 0] + bi;
                    float v1 = acc[mi][nj][h2 * 2 + 1] + bi;
                    if (Res) {
                        float2 r2 = *(const float2*)(Res + rowoff + col);
                        v0 += r2.x; v1 += r2.y;
                    }
                    if (act) {
                        v0 = v0 > 0.f ? v0 : expm1f(v0);
                        v1 = v1 > 0.f ? v1 : expm1f(v1);
                    }
                    *(__half2*)(Outh + rowoff + col) = __floats2half2_rn(v0, v1);
                }
            }
        }
    } else {
        __syncthreads();
        __half* smh = (__half*)smem;
        #pragma unroll
        for (int mi = 0; mi < 4; mi++) {
            #pragma unroll
            for (int h2 = 0; h2 < 2; h2++) {
                int ml = wm * 64 + mi * 16 + h2 * 8 + g;
                float bi = bias[mt * 128 + ml];
                #pragma unroll
                for (int nj = 0; nj < 4; nj++) {
                    int ll = wn * 32 + nj * 8 + 2 * tg;
                    float v0 = acc[mi][nj][h2 * 2 + 0] + bi;
                    float v1 = acc[mi][nj][h2 * 2 + 1] + bi;
                    if (act) {
                        v0 = v0 > 0.f ? v0 : expm1f(v0);
                        v1 = v1 > 0.f ? v1 : expm1f(v1);
                    }
                    smh[(uint32_t)ll * 136 + ml]       = __float2half(v0);
                    smh[(uint32_t)(ll + 1) * 136 + ml] = __float2half(v1);
                }
            }
        }
        __syncthreads();
        int rowbase = (lt & 1) * 128;
        int NCo = M >> 6;
        #pragma unroll
        for (int kc = 0; kc < 2; kc++) {
            char* db = (char*)(Outh + (((size_t)b * 16 + lt256) * NCo + (mt * 2 + kc)) * 16384);
            #pragma unroll
            for (int it = 0; it < 4; it++) {
                int u = tid + 256 * it;
                int row = u >> 3, j = u & 7;
                uint4 w = *(uint4*)&smh[(uint32_t)row * 136 + kc * 64 + j * 8];
                *(uint4*)(db + swz128((uint32_t)(rowbase + row) * 128 + j * 16)) = w;
            }
        }
    }
}

// ---------------------------------------------------------------------------
// ctx via tensor cores (exp folded). grid (64, NSPLIT), 256 threads.
// ---------------------------------------------------------------------------
__global__ __launch_bounds__(256) void ctx_mma(
    const __half* __restrict__ kk, const __half* __restrict__ vv,
    float* __restrict__ ctxp, float* __restrict__ zp)
{
    __shared__ __align__(1024) char smem[16384];
    uint32_t sb = smem_u32(smem);
    int bh = blockIdx.x, sp = blockIdx.y;
    int tid = threadIdx.x, wid = tid >> 5, lane = tid & 31;
    const __half* kb = kk + (size_t)bh * Dh * Ln;
    const __half* vb = vv + (size_t)bh * Dh * Ln;

    int lrow = tid >> 2;
    int lu = (tid & 3) * 2;
    uint32_t sw0 = swz128((uint32_t)lrow * 128 + lu * 16);
    uint32_t sw1 = swz128((uint32_t)lrow * 128 + lu * 16 + 16);

    int mtile = wid >> 1;
    int ntile = (wid & 1) * 32;
    int sub = lane >> 3, r7 = lane & 7;
    uint32_t aRowOff = (uint32_t)(mtile * 16 + (sub & 1) * 8 + r7) * 128;
    uint32_t aMask = (aRowOff >> 3) & 0x70;
    int kaddA = (sub >> 1) * 16;
    uint32_t bRowOff[2], bMask[2];
    int kaddB = (sub & 1) * 16;
    #pragma unroll
    for (int j = 0; j < 2; j++) {
        uint32_t row = (uint32_t)(ntile + j * 16 + (sub >> 1) * 8 + r7);
        bRowOff[j] = row * 128;
        bMask[j] = (bRowOff[j] >> 3) & 0x70;
    }

    float acc[4][4];
    #pragma unroll
    for (int i = 0; i < 4; i++)
        #pragma unroll
        for (int j = 0; j < 4; j++) acc[i][j] = 0.f;
    float zacc = 0.f;

    int lbeg = sp * (Ln / NSPLIT);
    const int NCH = (Ln / NSPLIT) / 64;
    for (int ch = 0; ch < NCH; ch++) {
        int l0 = lbeg + ch * 64;
        const __half* kr = kb + (size_t)lrow * Ln + l0 + lu * 8;
        const __half* vr = vb + (size_t)lrow * Ln + l0 + lu * 8;
        uint4 k0 = *(const uint4*)kr;
        uint4 k1 = *(const uint4*)(kr + 8);
        uint4 v0 = *(const uint4*)vr;
        uint4 v1 = *(const uint4*)(vr + 8);
        uint32_t* kw;
        kw = (uint32_t*)&k0;
        #pragma unroll
        for (int i = 0; i < 4; i++) {
            float2 f = __half22float2(*(__half2*)&kw[i]);
            f.x = __expf(f.x); f.y = __expf(f.y);
            zacc += f.x + f.y;
            kw[i] = pack2h(f.x, f.y);
        }
        kw = (uint32_t*)&k1;
        #pragma unroll
        for (int i = 0; i < 4; i++) {
            float2 f = __half22float2(*(__half2*)&kw[i]);
            f.x = __expf(f.x); f.y = __expf(f.y);
            zacc += f.x + f.y;
            kw[i] = pack2h(f.x, f.y);
        }
        __syncthreads();
        *(uint4*)(smem + sw0) = k0;
        *(uint4*)(smem + sw1) = k1;
        *(uint4*)(smem + 8192 + sw0) = v0;
        *(uint4*)(smem + 8192 + sw1) = v1;
        __syncthreads();
        #pragma unroll
        for (int kk2 = 0; kk2 < 4; kk2++) {
            int kbyte = kk2 * 32;
            uint32_t aa[4], bbv[8];
            LDSM4(aa, sb + aRowOff + (uint32_t)((kaddA + kbyte) ^ aMask));
            #pragma unroll
            for (int j = 0; j < 2; j++)
                LDSM4(&bbv[j * 4], sb + 8192 + bRowOff[j] + (uint32_t)((kaddB + kbyte) ^ bMask[j]));
            #pragma unroll
            for (int nj = 0; nj < 4; nj++)
                MMA16816(acc[nj], aa, &bbv[nj * 2]);
        }
    }

    int g = lane >> 2, tg = lane & 3;
    float* cbase = ctxp + ((size_t)sp * 64 + bh) * 4096;
    #pragma unroll
    for (int nj = 0; nj < 4; nj++) {
        int dv = ntile + nj * 8 + 2 * tg;
        int dk0 = mtile * 16 + g;
        *(float2*)(cbase + (size_t)dk0 * 64 + dv)       = make_float2(acc[nj][0], acc[nj][1]);
        *(float2*)(cbase + (size_t)(dk0 + 8) * 64 + dv) = make_float2(acc[nj][2], acc[nj][3]);
    }
    zacc += __shfl_xor_sync(0xFFFFFFFFu, zacc, 1);
    zacc += __shfl_xor_sync(0xFFFFFFFFu, zacc, 2);
    if ((tid & 3) == 0)
        zp[((size_t)sp * 64 + bh) * 64 + lrow] = zacc;
}

// ---------------------------------------------------------------------------
// ctx_reduce: reduce NSPLIT partials + Z-normalize ONCE -> fp32 ctxn (16KB/bh)
// grid (64), 256 threads.
// ---------------------------------------------------------------------------
__global__ __launch_bounds__(256) void ctx_reduce(
    const float* __restrict__ ctxp, const float* __restrict__ zp,
    float* __restrict__ ctxn)
{
    int bh = blockIdx.x;
    __shared__ float zinv[64];
    int tid = threadIdx.x;

    if (tid < 64) {
        float zs = 0.f;
        #pragma unroll
        for (int s = 0; s < NSPLIT; s++)
            zs += zp[((size_t)s * 64 + bh) * 64 + tid];
        zinv[tid] = 1.f / zs;
    }
    __syncthreads();

    float4* ob = (float4*)(ctxn + (size_t)bh * 4096);
    #pragma unroll
    for (int r = 0; r < 4; r++) {
        int idx = tid + 256 * r;          // float4 index 0..1023
        float zi = zinv[idx >> 4];
        float4 sum = make_float4(0.f, 0.f, 0.f, 0.f);
        #pragma unroll
        for (int s = 0; s < NSPLIT; s++) {
            const float4* p = (const float4*)(ctxp + ((size_t)s * 64 + bh) * 4096);
            float4 t = p[idx];
            sum.x += t.x; sum.y += t.y; sum.z += t.z; sum.w += t.w;
        }
        sum.x *= zi; sum.y *= zi; sum.z *= zi; sum.w *= zi;
        ob[idx] = sum;
    }
}

// ---------------------------------------------------------------------------
// att fused: load normalized ctx once, head-softmax(q fp16) inline with
// fp16-packed weights (register diet), fp16 tiled output.
// grid (16, 64), 256 threads.
// ---------------------------------------------------------------------------
__global__ __launch_bounds__(256) void att_fused(
    const float* __restrict__ ctxn, const __half* __restrict__ qh,
    __half* __restrict__ attc)
{
    int bh = blockIdx.y;
    int b = bh >> 3, h = bh & 7;
    __shared__ float cs[64][64];
    int tid = threadIdx.x;

    float4* cs4 = (float4*)cs;
    const float4* p = (const float4*)(ctxn + (size_t)bh * 4096);
    #pragma unroll
    for (int r = 0; r < 4; r++) {
        int idx = tid + 256 * r;
        cs4[idx] = p[idx];
    }
    __syncthreads();

    int l = blockIdx.x * 256 + tid;
    const __half* qb = qh + (size_t)bh * Dh * Ln + l;

    // phase 1: head softmax -> packed fp16 weights (32 regs)
    uint32_t qp[32];
    {
        float qv[64];
        float mx = -1e30f;
        #pragma unroll
        for (int d = 0; d < 64; d++) {
            qv[d] = __half2float(qb[(size_t)d * Ln]);
            mx = fmaxf(mx, qv[d]);
        }
        float s = 0.f;
        #pragma unroll
        for (int d = 0; d < 64; d++) { qv[d] = __expf(qv[d] - mx); s += qv[d]; }
        float inv = 1.f / s;
        #pragma unroll
        for (int dp = 0; dp < 32; dp++)
            qp[dp] = pack2h(qv[2 * dp] * inv, qv[2 * dp + 1] * inv);
    }

    // phase 2: matvec with unpacked weight pairs
    float acc[64];
    #pragma unroll
    for (int d = 0; d < 64; d++) acc[d] = 0.f;

    #pragma unroll 4
    for (int dp = 0; dp < 32; dp++) {
        float2 qq = __half22float2(*(__half2*)&qp[dp]);
        int dk0 = 2 * dp;
        #pragma unroll
        for (int j = 0; j < 16; j++) {
            float4 c0 = *(const float4*)&cs[dk0][j * 4];
            float4 c1 = *(const float4*)&cs[dk0 + 1][j * 4];
            acc[4 * j + 0] += c0.x * qq.x + c1.x * qq.y;
            acc[4 * j + 1] += c0.y * qq.x + c1.y * qq.y;
            acc[4 * j + 2] += c0.z * qq.x + c1.z * qq.y;
            acc[4 * j + 3] += c0.w * qq.x + c1.w * qq.y;
        }
    }

    char* db = (char*)(attc + (((size_t)b * 16 + blockIdx.x) * 8 + h) * 16384);
    #pragma unroll
    for (int j = 0; j < 8; j++) {
        uint4 w;
        w.x = pack2h(acc[8*j+0], acc[8*j+1]);
        w.y = pack2h(acc[8*j+2], acc[8*j+3]);
        w.z = pack2h(acc[8*j+4], acc[8*j+5]);
        w.w = pack2h(acc[8*j+6], acc[8*j+7]);
        *(uint4*)(db + swz128((uint32_t)tid * 128 + j * 16)) = w;
    }
}

// ---------------------------------------------------------------------------
// Channel LayerNorm over C=512, fp16 in -> fp32 out (single pass, reg cache)
// ---------------------------------------------------------------------------
__global__ __launch_bounds__(256) void ln_kernel(
    const __half* __restrict__ in, float* __restrict__ out,
    const float* __restrict__ g, const float* __restrict__ be)
{
    __shared__ float ss[8][32], sq[8][32], smean[32], srstd[32];
    int blk = blockIdx.x;
    int b = blk >> 7;
    int li = threadIdx.x & 31;
    int l = ((blk & 127) << 5) + li;
    int r = threadIdx.x >> 5;
    const __half* base = in + (size_t)b * Cc * Ln + l;

    float s = 0.f, s2 = 0.f;
    float x0[64];
    #pragma unroll
    for (int k2 = 0; k2 < 64; k2++) {
        int c = r * 64 + k2;
        float x = __half2float(base[(size_t)c * Ln]);
        x0[k2] = x;
        s += x; s2 += x * x;
    }
    ss[r][li] = s; sq[r][li] = s2;
    __syncthreads();
    if (r == 0) {
        float ts = ss[0][li], t2 = sq[0][li];
        #pragma unroll
        for (int rr = 1; rr < 8; rr++) { ts += ss[rr][li]; t2 += sq[rr][li]; }
        float mean = ts * (1.f / 512.f);
        float var = t2 * (1.f / 512.f) - mean * mean;
        smean[li] = mean;
        srstd[li] = rsqrtf(var + 1e-5f);
    }
    __syncthreads();
    float mean = smean[li], rstd = srstd[li];
    float* ob = out + (size_t)b * Cc * Ln + l;
    #pragma unroll
    for (int k2 = 0; k2 < 64; k2++) {
        int c = r * 64 + k2;
        ob[(size_t)c * Ln] = (x0[k2] - mean) * rstd * g[c] + be[c];
    }
}

// ---------------------------------------------------------------------------
// Channel LayerNorm, fp16 in -> fp16 tiled out
// ---------------------------------------------------------------------------
__global__ __launch_bounds__(256) void ln_h(
    const __half* __restrict__ in, __half* __restrict__ outc,
    const float* __restrict__ g, const float* __restrict__ be)
{
    __shared__ float ss[8][32], sq[8][32], smean[32], srstd[32];
    int blk = blockIdx.x;
    int b = blk >> 7;
    int li = threadIdx.x & 31;
    int l = ((blk & 127) << 5) + li;
    int r = threadIdx.x >> 5;
    const __half* base = in + (size_t)b * Cc * Ln + l;

    float s = 0.f, s2 = 0.f;
    float x0[64];
    #pragma unroll
    for (int k2 = 0; k2 < 64; k2++) {
        int c = r * 64 + k2;
        float x = __half2float(base[(size_t)c * Ln]);
        x0[k2] = x;
        s += x; s2 += x * x;
    }
    ss[r][li] = s; sq[r][li] = s2;
    __syncthreads();
    if (r == 0) {
        float ts = ss[0][li], t2 = sq[0][li];
        #pragma unroll
        for (int rr = 1; rr < 8; rr++) { ts += ss[rr][li]; t2 += sq[rr][li]; }
        float mean = ts * (1.f / 512.f);
        float var = t2 * (1.f / 512.f) - mean * mean;
        smean[li] = mean;
        srstd[li] = rsqrtf(var + 1e-5f);
    }
    __syncthreads();
    float mean = smean[li], rstd = srstd[li];

    char* db = (char*)(outc + (((size_t)b * 16 + (l >> 8)) * 8 + r) * 16384);
    uint32_t row = (uint32_t)(l & 255);
    #pragma unroll
    for (int j = 0; j < 8; j++) {
        float v[8];
        #pragma unroll
        for (int q2 = 0; q2 < 8; q2++) {
            int c = r * 64 + j * 8 + q2;
            v[q2] = (x0[j * 8 + q2] - mean) * rstd * g[c] + be[c];
        }
        uint4 w;
        w.x = pack2h(v[0], v[1]);
        w.y = pack2h(v[2], v[3]);
        w.z = pack2h(v[4], v[5]);
        w.w = pack2h(v[6], v[7]);
        *(uint4*)(db + swz128(row * 128 + j * 16)) = w;
    }
}

// ---------------------------------------------------------------------------
extern "C" void kernel_launch(void* const* d_in, const int* in_sizes, int n_in,
                              void* d_out, int out_size)
{
    const float* z1  = (const float*)d_in[0];
    const float* z2  = (const float*)d_in[1];
    const float* Wq  = (const float*)d_in[2];
    const float* bq  = (const float*)d_in[3];
    const float* Wk  = (const float*)d_in[4];
    const float* bkb = (const float*)d_in[5];
    const float* Wv  = (const float*)d_in[6];
    const float* bv  = (const float*)d_in[7];
    const float* Wr  = (const float*)d_in[8];
    const float* br  = (const float*)d_in[9];
    const float* g1  = (const float*)d_in[10];
    const float* be1 = (const float*)d_in[11];
    const float* W1  = (const float*)d_in[12];
    const float* b1  = (const float*)d_in[13];
    const float* W2  = (const float*)d_in[14];
    const float* b2  = (const float*)d_in[15];
    const float* g2  = (const float*)d_in[16];
    const float* be2 = (const float*)d_in[17];

    float* fs = nullptr;
    cudaGetSymbolAddress((void**)&fs, g_scratch);
    __half* hf = nullptr;
    cudaGetSymbolAddress((void**)&hf, g_hf);

    const size_t SZ = (size_t)Bn * Cc * Ln;   // 16777216
    __half* qh  = (__half*)(fs);
    __half* kh  = (__half*)(fs + SZ);
    __half* vh  = (__half*)(fs + 2 * SZ);
    __half* zh  = (__half*)(fs + 4 * SZ);
    __half* yh  = (__half*)(fs + 5 * SZ);
    float* ctxp = fs + 6 * SZ;                 // NSPLIT*64*64*64 floats (16.8M)
    float* zp   = fs + 6 * SZ + 4194304;       // NSPLIT*64*64 floats
    float* ctxn = fs + 6 * SZ + 4325376;       // 64*4096 floats

    cudaFuncSetAttribute(gemm_wm, cudaFuncAttributeMaxDynamicSharedMemorySize, GEMM_SMEM);
    cudaFuncSetAttribute(gemm_qkv, cudaFuncAttributeMaxDynamicSharedMemorySize, GEMM_SMEM);

    dim3 thr(256);
    conv_w_all<<<dim3(16, 8, 6), thr>>>(Wq, Wk, Wv, Wr, W1, W2, hf);
    conv_x2<<<dim3(8, 16, 16), thr>>>(z1, z2, hf + OFF_Z1C, hf + OFF_Z2C);

    // Merged Q/K/V projections (all fp16 flat)
    gemm_qkv<<<dim3(4, 32, 24), thr, GEMM_SMEM>>>(hf, bq, bkb, bv, qh, kh, vh);

    // Attention core: ctx on tensor cores, one-shot reduce, scalar apply
    ctx_mma<<<dim3(Bn * Hh, NSPLIT), thr>>>(kh, vh, ctxp, zp);
    ctx_reduce<<<Bn * Hh, thr>>>(ctxp, zp, ctxn);
    att_fused<<<dim3(Ln / 256, Bn * Hh), thr>>>(ctxn, qh, hf + OFF_ATTC);

    // Reprojection + residual -> fp16 flat z
    gemm_wm<<<dim3(4, 32, 8), thr, GEMM_SMEM>>>(hf + OFF_WR, br, hf + OFF_ATTC, nullptr, zh, z1, 512, 512, 0, 2);

    // LN1 (fp16 in) -> fp16 tiled
    ln_h<<<Bn * (Ln / 32), thr>>>(zh, hf + OFF_ZC, g1, be1);

    // FFN1 -> fp16 tiled h (ELU fused), FFN2 -> fp16 flat y
    gemm_wm<<<dim3(8, 32, 8), thr, GEMM_SMEM>>>(hf + OFF_W1, b1, hf + OFF_ZC, nullptr, hf + OFF_HC, nullptr, 1024, 512, 1, 1);
    gemm_wm<<<dim3(4, 32, 8), thr, GEMM_SMEM>>>(hf + OFF_W2, b2, hf + OFF_HC, nullptr, yh, nullptr, 512, 1024, 0, 2);

    // LN2 (fp16 in) -> fp32 output
    ln_kernel<<<Bn * (Ln / 32), thr>>>(yh, (float*)d_out, g2, be2);
}

// round 15
// speedup vs baseline: 1.0105x; 1.0105x over previous
#include <cuda_runtime.h>
#include <cuda_fp16.h>
#include <cstdint>

// Problem constants
#define Bn  8
#define Cc  512
#define Ln  4096
#define Hh  8
#define Dh  64
#define NSPLIT 8

// ---------------------------------------------------------------------------
// Scratch
// ---------------------------------------------------------------------------
__device__ float g_scratch[135266304];
__device__ __half g_hf[102760448];

// half-element offsets into g_hf
#define OFF_Z1C  0ull
#define OFF_Z2C  16777216ull
#define OFF_ATTC 33554432ull
#define OFF_ZC   50331648ull
#define OFF_HC   67108864ull
#define OFF_WQ   100663296ull
#define OFF_WK   100925440ull
#define OFF_WV   101187584ull
#define OFF_WR   101449728ull
#define OFF_W1   101711872ull
#define OFF_W2   102236160ull

// ---------------------------------------------------------------------------
// Helpers
// ---------------------------------------------------------------------------
__device__ __forceinline__ uint32_t smem_u32(const void* p) {
    uint32_t a;
    asm("{ .reg .u64 t; cvta.to.shared.u64 t, %1; cvt.u32.u64 %0, t; }"
        : "=r"(a) : "l"(p));
    return a;
}
__device__ __host__ __forceinline__ uint32_t swz128(uint32_t off) {
    return off ^ ((off >> 3) & 0x70);
}
__device__ __forceinline__ void cpasync16(uint32_t d, const void* s) {
    asm volatile("cp.async.cg.shared.global [%0], [%1], 16;" :: "r"(d), "l"(s));
}
#define CP_COMMIT() asm volatile("cp.async.commit_group;" ::: "memory")
#define CP_WAIT(N)  asm volatile("cp.async.wait_group " #N ";" ::: "memory")

#define LDSM4(R, ADDR) \
    asm volatile("ldmatrix.sync.aligned.m8n8.x4.shared.b16 {%0,%1,%2,%3}, [%4];" \
        : "=r"((R)[0]), "=r"((R)[1]), "=r"((R)[2]), "=r"((R)[3]) : "r"(ADDR))

#define MMA16816(C, A, Bv) \
    asm volatile("mma.sync.aligned.m16n8k16.row.col.f32.f16.f16.f32 " \
        "{%0,%1,%2,%3}, {%4,%5,%6,%7}, {%8,%9}, {%0,%1,%2,%3};" \
        : "+f"((C)[0]), "+f"((C)[1]), "+f"((C)[2]), "+f"((C)[3]) \
        : "r"((A)[0]), "r"((A)[1]), "r"((A)[2]), "r"((A)[3]), \
          "r"((Bv)[0]), "r"((Bv)[1]))

__device__ __forceinline__ uint32_t pack2h(float a, float b) {
    __half2 h = __floats2half2_rn(a, b);
    return *(uint32_t*)&h;
}

#define STG 32768u
#define GEMM_SMEM 98304   // 3 stages

// ---------------------------------------------------------------------------
// Convert ALL weights in one launch. grid (16, 8, 6)
// ---------------------------------------------------------------------------
__global__ __launch_bounds__(256) void conv_w_all(
    const float* __restrict__ Wq, const float* __restrict__ Wk,
    const float* __restrict__ Wv, const float* __restrict__ Wr,
    const float* __restrict__ W1, const float* __restrict__ W2,
    __half* __restrict__ hf)
{
    int widx = blockIdx.z;
    const float* src;
    __half* dstb;
    int K, MT;
    switch (widx) {
        case 0: src = Wq; dstb = hf + OFF_WQ; K = 512;  MT = 4; break;
        case 1: src = Wk; dstb = hf + OFF_WK; K = 512;  MT = 4; break;
        case 2: src = Wv; dstb = hf + OFF_WV; K = 512;  MT = 4; break;
        case 3: src = Wr; dstb = hf + OFF_WR; K = 512;  MT = 4; break;
        case 4: src = W1; dstb = hf + OFF_W1; K = 512;  MT = 8; break;
        default: src = W2; dstb = hf + OFF_W2; K = 1024; MT = 4; break;
    }
    int NC = K >> 6;
    int kc = blockIdx.x, mt = blockIdx.y;
    if (kc >= NC || mt >= MT) return;
    char* db = (char*)(dstb + ((size_t)(mt * NC + kc)) * 8192);
    const float* sb = src + ((size_t)mt * 128) * K + kc * 64;
    for (int it = 0; it < 4; it++) {
        int u = threadIdx.x + 256 * it;
        int r = u >> 3, g = u & 7;
        float x0[8];
        #pragma unroll
        for (int q = 0; q < 2; q++) {
            float4 v = *(const float4*)(sb + (size_t)r * K + g * 8 + q * 4);
            x0[q*4+0]=v.x; x0[q*4+1]=v.y; x0[q*4+2]=v.z; x0[q*4+3]=v.w;
        }
        uint4 w;
        w.x = pack2h(x0[0], x0[1]);
        w.y = pack2h(x0[2], x0[3]);
        w.z = pack2h(x0[4], x0[5]);
        w.w = pack2h(x0[6], x0[7]);
        uint32_t sw = swz128((uint32_t)r * 128 + g * 16);
        *(uint4*)(db + sw) = w;
    }
}

// ---------------------------------------------------------------------------
// Convert+transpose z1 and z2 in one launch: grid (8, 16, 16)
// ---------------------------------------------------------------------------
__global__ __launch_bounds__(256) void conv_x2(
    const float* __restrict__ src1, const float* __restrict__ src2,
    __half* __restrict__ dst1, __half* __restrict__ dst2)
{
    const int K = 512;
    int kc = blockIdx.x, lt = blockIdx.y;
    int b = blockIdx.z & 7;
    const float* src = (blockIdx.z < 8) ? src1 : src2;
    __half* dstb = (blockIdx.z < 8) ? dst1 : dst2;
    int NC = K >> 6;
    __shared__ float sm[32][264];
    const float* sb = src + ((size_t)b * K + kc * 64) * Ln + (size_t)lt * 256;
    char* db = (char*)(dstb + (((size_t)b * 16 + lt) * NC + kc) * 16384);
    int t = threadIdx.x;
    for (int p = 0; p < 2; p++) {
        __syncthreads();
        #pragma unroll
        for (int i = 0; i < 8; i++) {
            int u = t + 256 * i;
            int kr = u >> 6;
            int lc = u & 63;
            float4 v = *(const float4*)(sb + ((size_t)(p * 32 + kr)) * Ln + lc * 4);
            sm[kr][lc*4+0]=v.x; sm[kr][lc*4+1]=v.y; sm[kr][lc*4+2]=v.z; sm[kr][lc*4+3]=v.w;
        }
        __syncthreads();
        #pragma unroll
        for (int g = 0; g < 4; g++) {
            float x0[8];
            #pragma unroll
            for (int j = 0; j < 8; j++) x0[j] = sm[g*8+j][t];
            uint4 w;
            w.x = pack2h(x0[0], x0[1]);
            w.y = pack2h(x0[2], x0[3]);
            w.z = pack2h(x0[4], x0[5]);
            w.w = pack2h(x0[6], x0[7]);
            uint32_t sw = swz128((uint32_t)t * 128 + (p * 32 + g * 8) * 2);
            *(uint4*)(db + sw) = w;
        }
    }
}

// ---------------------------------------------------------------------------
// Shared GEMM mainloop (256 threads, 8 warps 64x32, 128x128 tile, 3 stages)
// ---------------------------------------------------------------------------
#define GEMM_PROLOGUE() \
    uint32_t sbase = smem_u32(smem); \
    int tid = threadIdx.x, wid = tid >> 5, lane = tid & 31; \
    int wm = wid >> 2, wn = wid & 3; \
    int sub = lane >> 3, r = lane & 7; \
    uint32_t aRow[4], aMask[4]; \
    int kaddA = (sub >> 1) * 16; \
    _Pragma("unroll") \
    for (int i = 0; i < 4; i++) { \
        uint32_t row = wm * 64 + i * 16 + (sub & 1) * 8 + r; \
        aRow[i] = row * 128; \
        aMask[i] = (aRow[i] >> 3) & 0x70; \
    } \
    uint32_t bRow[2], bMask[2]; \
    int kaddB = (sub & 1) * 16; \
    _Pragma("unroll") \
    for (int j = 0; j < 2; j++) { \
        uint32_t row = wn * 32 + j * 16 + (sub >> 1) * 8 + r; \
        bRow[j] = row * 128; \
        bMask[j] = (bRow[j] >> 3) & 0x70; \
    } \
    float acc[4][4][4]; \
    _Pragma("unroll") \
    for (int i = 0; i < 4; i++) \
        _Pragma("unroll") \
        for (int j = 0; j < 4; j++) \
            _Pragma("unroll") \
            for (int q = 0; q < 4; q++) acc[i][j][q] = 0.f;

#define GEMM_LOAD_STAGE(kc, s) do { \
    uint32_t S = sbase + (uint32_t)(s) * STG; \
    const char* ah = Abase + (size_t)(kc) * 16384; \
    const char* bh = Bbase + (size_t)(kc) * 32768; \
    _Pragma("unroll") \
    for (int q = 0; q < 4; q++) { \
        uint32_t off = (uint32_t)tid * 64 + q * 16; \
        cpasync16(S + off,         ah + off); \
        cpasync16(S + 16384 + off, bh + off); \
    } \
} while (0)

#define GEMM_MAINLOOP(NC) \
    GEMM_LOAD_STAGE(0, 0); CP_COMMIT(); \
    if ((NC) > 1) { GEMM_LOAD_STAGE(1, 1); CP_COMMIT(); } \
    int sc = 0; \
    for (int c = 0; c < (NC); c++) { \
        CP_WAIT(1); \
        __syncthreads(); \
        if (c + 2 < (NC)) { \
            int s2 = sc + 2; if (s2 >= 3) s2 -= 3; \
            GEMM_LOAD_STAGE(c + 2, s2); CP_COMMIT(); \
        } \
        uint32_t S = sbase + (uint32_t)sc * STG; \
        _Pragma("unroll") \
        for (int kk = 0; kk < 4; kk++) { \
            int kb = kk * 32; \
            uint32_t aa[16], bb[8]; \
            _Pragma("unroll") \
            for (int i = 0; i < 4; i++) \
                LDSM4(&aa[i * 4], S + aRow[i] + (uint32_t)((kaddA + kb) ^ aMask[i])); \
            _Pragma("unroll") \
            for (int j = 0; j < 2; j++) \
                LDSM4(&bb[j * 4], S + 16384 + bRow[j] + (uint32_t)((kaddB + kb) ^ bMask[j])); \
            _Pragma("unroll") \
            for (int mi = 0; mi < 4; mi++) \
                _Pragma("unroll") \
                for (int nj = 0; nj < 4; nj++) \
                    MMA16816(acc[mi][nj], &aa[mi * 4], &bb[nj * 2]); \
        } \
        sc++; if (sc == 3) sc = 0; \
    }

// ---------------------------------------------------------------------------
// Merged Q/K/V projection GEMM: grid (4, 32, 24); z>>3 selects {Q,K,V}.
// All outputs fp16 flat [B, C, L].
// ---------------------------------------------------------------------------
__global__ __launch_bounds__(256, 2) void gemm_qkv(
    const __half* __restrict__ hf,
    const float* __restrict__ bq, const float* __restrict__ bk,
    const float* __restrict__ bv,
    __half* __restrict__ qh, __half* __restrict__ kh, __half* __restrict__ vh)
{
    extern __shared__ __align__(1024) char smem[];
    const int NC = 8;
    int mt = blockIdx.x, lt = blockIdx.y;
    int which = blockIdx.z >> 3, b = blockIdx.z & 7;

    const __half* Wc = (which == 0) ? hf + OFF_WQ : (which == 1) ? hf + OFF_WK : hf + OFF_WV;
    const float* bias = (which == 0) ? bq : (which == 1) ? bk : bv;
    const __half* Xc = (which == 0) ? hf + OFF_Z1C : hf + OFF_Z2C;
    __half* Out = (which == 0) ? qh : (which == 1) ? kh : vh;

    const char* Abase = (const char*)Wc + ((size_t)mt * NC) * 16384;
    int lt256 = lt >> 1, half = lt & 1;
    const char* Bbase = (const char*)Xc + (((size_t)b * 16 + lt256) * NC) * 32768
                        + (size_t)half * 16384;

    GEMM_PROLOGUE();
    GEMM_MAINLOOP(NC);

    int g = lane >> 2, tg = lane & 3;
    #pragma unroll
    for (int mi = 0; mi < 4; mi++) {
        #pragma unroll
        for (int h2 = 0; h2 < 2; h2++) {
            int m = mt * 128 + wm * 64 + mi * 16 + h2 * 8 + g;
            float bi = bias[m];
            size_t rowoff = ((size_t)b * 512 + m) * Ln + (size_t)lt * 128 + wn * 32;
            #pragma unroll
            for (int nj = 0; nj < 4; nj++) {
                int col = nj * 8 + 2 * tg;
                float v0 = acc[mi][nj][h2 * 2 + 0] + bi;
                float v1 = acc[mi][nj][h2 * 2 + 1] + bi;
                *(__half2*)(Out + rowoff + col) = __floats2half2_rn(v0, v1);
            }
        }
    }
}

// ---------------------------------------------------------------------------
// General GEMM. outmode 0: fp32 Out (+Res)(+ELU). outmode 1: fp16 tiled Outh.
// outmode 2: fp16 flat Outh (+Res fp32)(+ELU).
// ---------------------------------------------------------------------------
__global__ __launch_bounds__(256, 2) void gemm_wm(
    const __half* __restrict__ Wc, const float* __restrict__ bias,
    const __half* __restrict__ Xc, float* __restrict__ Out,
    __half* __restrict__ Outh,
    const float* __restrict__ Res, int M, int K, int act, int outmode)
{
    extern __shared__ __align__(1024) char smem[];
    const int NC = K >> 6;
    int mt = blockIdx.x, lt = blockIdx.y, b = blockIdx.z;

    const char* Abase = (const char*)Wc + ((size_t)mt * NC) * 16384;
    int lt256 = lt >> 1, half = lt & 1;
    const char* Bbase = (const char*)Xc + (((size_t)b * 16 + lt256) * NC) * 32768
                        + (size_t)half * 16384;

    GEMM_PROLOGUE();
    GEMM_MAINLOOP(NC);

    int g = lane >> 2, tg = lane & 3;

    if (outmode == 0) {
        #pragma unroll
        for (int mi = 0; mi < 4; mi++) {
            #pragma unroll
            for (int h2 = 0; h2 < 2; h2++) {
                int m = mt * 128 + wm * 64 + mi * 16 + h2 * 8 + g;
                float bi = bias[m];
                size_t rowoff = ((size_t)b * M + m) * Ln + (size_t)lt * 128 + wn * 32;
                #pragma unroll
                for (int nj = 0; nj < 4; nj++) {
                    int col = nj * 8 + 2 * tg;
                    float v0 = acc[mi][nj][h2 * 2 + 0] + bi;
                    float v1 = acc[mi][nj][h2 * 2 + 1] + bi;
                    if (Res) {
                        float2 r2 = *(const float2*)(Res + rowoff + col);
                        v0 += r2.x; v1 += r2.y;
                    }
                    if (act) {
                        v0 = v0 > 0.f ? v0 : expm1f(v0);
                        v1 = v1 > 0.f ? v1 : expm1f(v1);
                    }
                    *(float2*)(Out + rowoff + col) = make_float2(v0, v1);
                }
            }
        }
    } else if (outmode == 2) {
        #pragma unroll
        for (int mi = 0; mi < 4; mi++) {
            #pragma unroll
            for (int h2 = 0; h2 < 2; h2++) {
                int m = mt * 128 + wm * 64 + mi * 16 + h2 * 8 + g;
                float bi = bias[m];
                size_t rowoff = ((size_t)b * M + m) * Ln + (size_t)lt * 128 + wn * 32;
                #pragma unroll
                for (int nj = 0; nj < 4; nj++) {
                    int col = nj * 8 + 2 * tg;
                    float v0 = acc[mi][nj][h2 * 2 + 0] + bi;
                    float v1 = acc[mi][nj][h2 * 2 + 1] + bi;
                    if (Res) {
                        float2 r2 = *(const float2*)(Res + rowoff + col);
                        v0 += r2.x; v1 += r2.y;
                    }
                    if (act) {
                        v0 = v0 > 0.f ? v0 : expm1f(v0);
                        v1 = v1 > 0.f ? v1 : expm1f(v1);
                    }
                    *(__half2*)(Outh + rowoff + col) = __floats2half2_rn(v0, v1);
                }
            }
        }
    } else {
        __syncthreads();
        __half* smh = (__half*)smem;
        #pragma unroll
        for (int mi = 0; mi < 4; mi++) {
            #pragma unroll
            for (int h2 = 0; h2 < 2; h2++) {
                int ml = wm * 64 + mi * 16 + h2 * 8 + g;
                float bi = bias[mt * 128 + ml];
                #pragma unroll
                for (int nj = 0; nj < 4; nj++) {
                    int ll = wn * 32 + nj * 8 + 2 * tg;
                    float v0 = acc[mi][nj][h2 * 2 + 0] + bi;
                    float v1 = acc[mi][nj][h2 * 2 + 1] + bi;
                    if (act) {
                        v0 = v0 > 0.f ? v0 : expm1f(v0);
                        v1 = v1 > 0.f ? v1 : expm1f(v1);
                    }
                    smh[(uint32_t)ll * 136 + ml]       = __float2half(v0);
                    smh[(uint32_t)(ll + 1) * 136 + ml] = __float2half(v1);
                }
            }
        }
        __syncthreads();
        int rowbase = (lt & 1) * 128;
        int NCo = M >> 6;
        #pragma unroll
        for (int kc = 0; kc < 2; kc++) {
            char* db = (char*)(Outh + (((size_t)b * 16 + lt256) * NCo + (mt * 2 + kc)) * 16384);
            #pragma unroll
            for (int it = 0; it < 4; it++) {
                int u = tid + 256 * it;
                int row = u >> 3, j = u & 7;
                uint4 w = *(uint4*)&smh[(uint32_t)row * 136 + kc * 64 + j * 8];
                *(uint4*)(db + swz128((uint32_t)(rowbase + row) * 128 + j * 16)) = w;
            }
        }
    }
}

// ---------------------------------------------------------------------------
// ctx via tensor cores (exp folded), double-buffered smem, ONE sync/chunk.
// grid (64, NSPLIT), 256 threads. Buffers: [k 8K][v 8K] x 2 = 32KB.
// ---------------------------------------------------------------------------
__global__ __launch_bounds__(256) void ctx_mma(
    const __half* __restrict__ kk, const __half* __restrict__ vv,
    float* __restrict__ ctxp, float* __restrict__ zp)
{
    __shared__ __align__(1024) char smem[32768];
    uint32_t sb = smem_u32(smem);
    int bh = blockIdx.x, sp = blockIdx.y;
    int tid = threadIdx.x, wid = tid >> 5, lane = tid & 31;
    const __half* kb = kk + (size_t)bh * Dh * Ln;
    const __half* vb = vv + (size_t)bh * Dh * Ln;

    int lrow = tid >> 2;
    int lu = (tid & 3) * 2;
    uint32_t sw0 = swz128((uint32_t)lrow * 128 + lu * 16);
    uint32_t sw1 = swz128((uint32_t)lrow * 128 + lu * 16 + 16);

    int mtile = wid >> 1;
    int ntile = (wid & 1) * 32;
    int sub = lane >> 3, r7 = lane & 7;
    uint32_t aRowOff = (uint32_t)(mtile * 16 + (sub & 1) * 8 + r7) * 128;
    uint32_t aMask = (aRowOff >> 3) & 0x70;
    int kaddA = (sub >> 1) * 16;
    uint32_t bRowOff[2], bMask[2];
    int kaddB = (sub & 1) * 16;
    #pragma unroll
    for (int j = 0; j < 2; j++) {
        uint32_t row = (uint32_t)(ntile + j * 16 + (sub >> 1) * 8 + r7);
        bRowOff[j] = row * 128;
        bMask[j] = (bRowOff[j] >> 3) & 0x70;
    }

    float acc[4][4];
    #pragma unroll
    for (int i = 0; i < 4; i++)
        #pragma unroll
        for (int j = 0; j < 4; j++) acc[i][j] = 0.f;
    float zacc = 0.f;

    int lbeg = sp * (Ln / NSPLIT);
    const int NCH = (Ln / NSPLIT) / 64;   // 8
    for (int ch = 0; ch < NCH; ch++) {
        int l0 = lbeg + ch * 64;
        uint32_t buf = (uint32_t)(ch & 1) * 16384;
        const __half* kr = kb + (size_t)lrow * Ln + l0 + lu * 8;
        const __half* vr = vb + (size_t)lrow * Ln + l0 + lu * 8;
        uint4 k0 = *(const uint4*)kr;
        uint4 k1 = *(const uint4*)(kr + 8);
        uint4 v0 = *(const uint4*)vr;
        uint4 v1 = *(const uint4*)(vr + 8);
        uint32_t* kw;
        kw = (uint32_t*)&k0;
        #pragma unroll
        for (int i = 0; i < 4; i++) {
            float2 f = __half22float2(*(__half2*)&kw[i]);
            f.x = __expf(f.x); f.y = __expf(f.y);
            zacc += f.x + f.y;
            kw[i] = pack2h(f.x, f.y);
        }
        kw = (uint32_t*)&k1;
        #pragma unroll
        for (int i = 0; i < 4; i++) {
            float2 f = __half22float2(*(__half2*)&kw[i]);
            f.x = __expf(f.x); f.y = __expf(f.y);
            zacc += f.x + f.y;
            kw[i] = pack2h(f.x, f.y);
        }
        *(uint4*)(smem + buf + sw0) = k0;
        *(uint4*)(smem + buf + sw1) = k1;
        *(uint4*)(smem + buf + 8192 + sw0) = v0;
        *(uint4*)(smem + buf + 8192 + sw1) = v1;
        __syncthreads();
        #pragma unroll
        for (int kk2 = 0; kk2 < 4; kk2++) {
            int kbyte = kk2 * 32;
            uint32_t aa[4], bbv[8];
            LDSM4(aa, sb + buf + aRowOff + (uint32_t)((kaddA + kbyte) ^ aMask));
            #pragma unroll
            for (int j = 0; j < 2; j++)
                LDSM4(&bbv[j * 4], sb + buf + 8192 + bRowOff[j] + (uint32_t)((kaddB + kbyte) ^ bMask[j]));
            #pragma unroll
            for (int nj = 0; nj < 4; nj++)
                MMA16816(acc[nj], aa, &bbv[nj * 2]);
        }
    }

    int g = lane >> 2, tg = lane & 3;
    float* cbase = ctxp + ((size_t)sp * 64 + bh) * 4096;
    #pragma unroll
    for (int nj = 0; nj < 4; nj++) {
        int dv = ntile + nj * 8 + 2 * tg;
        int dk0 = mtile * 16 + g;
        *(float2*)(cbase + (size_t)dk0 * 64 + dv)       = make_float2(acc[nj][0], acc[nj][1]);
        *(float2*)(cbase + (size_t)(dk0 + 8) * 64 + dv) = make_float2(acc[nj][2], acc[nj][3]);
    }
    zacc += __shfl_xor_sync(0xFFFFFFFFu, zacc, 1);
    zacc += __shfl_xor_sync(0xFFFFFFFFu, zacc, 2);
    if ((tid & 3) == 0)
        zp[((size_t)sp * 64 + bh) * 64 + lrow] = zacc;
}

// ---------------------------------------------------------------------------
// ctx_reduce: reduce NSPLIT partials + Z-normalize ONCE -> fp32 ctxn (16KB/bh)
// grid (64), 256 threads.
// ---------------------------------------------------------------------------
__global__ __launch_bounds__(256) void ctx_reduce(
    const float* __restrict__ ctxp, const float* __restrict__ zp,
    float* __restrict__ ctxn)
{
    int bh = blockIdx.x;
    __shared__ float zinv[64];
    int tid = threadIdx.x;

    if (tid < 64) {
        float zs = 0.f;
        #pragma unroll
        for (int s = 0; s < NSPLIT; s++)
            zs += zp[((size_t)s * 64 + bh) * 64 + tid];
        zinv[tid] = 1.f / zs;
    }
    __syncthreads();

    float4* ob = (float4*)(ctxn + (size_t)bh * 4096);
    #pragma unroll
    for (int r = 0; r < 4; r++) {
        int idx = tid + 256 * r;          // float4 index 0..1023
        float zi = zinv[idx >> 4];
        float4 sum = make_float4(0.f, 0.f, 0.f, 0.f);
        #pragma unroll
        for (int s = 0; s < NSPLIT; s++) {
            const float4* p = (const float4*)(ctxp + ((size_t)s * 64 + bh) * 4096);
            float4 t = p[idx];
            sum.x += t.x; sum.y += t.y; sum.z += t.z; sum.w += t.w;
        }
        sum.x *= zi; sum.y *= zi; sum.z *= zi; sum.w *= zi;
        ob[idx] = sum;
    }
}

// ---------------------------------------------------------------------------
// att fused: load normalized ctx once, head-softmax(q fp16) inline with
// fp16-packed weights, fp16 tiled output. grid (16, 64), 256 threads.
// ---------------------------------------------------------------------------
__global__ __launch_bounds__(256) void att_fused(
    const float* __restrict__ ctxn, const __half* __restrict__ qh,
    __half* __restrict__ attc)
{
    int bh = blockIdx.y;
    int b = bh >> 3, h = bh & 7;
    __shared__ float cs[64][64];
    int tid = threadIdx.x;

    float4* cs4 = (float4*)cs;
    const float4* p = (const float4*)(ctxn + (size_t)bh * 4096);
    #pragma unroll
    for (int r = 0; r < 4; r++) {
        int idx = tid + 256 * r;
        cs4[idx] = p[idx];
    }
    __syncthreads();

    int l = blockIdx.x * 256 + tid;
    const __half* qb = qh + (size_t)bh * Dh * Ln + l;

    // phase 1: head softmax -> packed fp16 weights (32 regs)
    uint32_t qp[32];
    {
        float qv[64];
        float mx = -1e30f;
        #pragma unroll
        for (int d = 0; d < 64; d++) {
            qv[d] = __half2float(qb[(size_t)d * Ln]);
            mx = fmaxf(mx, qv[d]);
        }
        float s = 0.f;
        #pragma unroll
        for (int d = 0; d < 64; d++) { qv[d] = __expf(qv[d] - mx); s += qv[d]; }
        float inv = 1.f / s;
        #pragma unroll
        for (int dp = 0; dp < 32; dp++)
            qp[dp] = pack2h(qv[2 * dp] * inv, qv[2 * dp + 1] * inv);
    }

    // phase 2: matvec with unpacked weight pairs
    float acc[64];
    #pragma unroll
    for (int d = 0; d < 64; d++) acc[d] = 0.f;

    #pragma unroll 4
    for (int dp = 0; dp < 32; dp++) {
        float2 qq = __half22float2(*(__half2*)&qp[dp]);
        int dk0 = 2 * dp;
        #pragma unroll
        for (int j = 0; j < 16; j++) {
            float4 c0 = *(const float4*)&cs[dk0][j * 4];
            float4 c1 = *(const float4*)&cs[dk0 + 1][j * 4];
            acc[4 * j + 0] += c0.x * qq.x + c1.x * qq.y;
            acc[4 * j + 1] += c0.y * qq.x + c1.y * qq.y;
            acc[4 * j + 2] += c0.z * qq.x + c1.z * qq.y;
            acc[4 * j + 3] += c0.w * qq.x + c1.w * qq.y;
        }
    }

    char* db = (char*)(attc + (((size_t)b * 16 + blockIdx.x) * 8 + h) * 16384);
    #pragma unroll
    for (int j = 0; j < 8; j++) {
        uint4 w;
        w.x = pack2h(acc[8*j+0], acc[8*j+1]);
        w.y = pack2h(acc[8*j+2], acc[8*j+3]);
        w.z = pack2h(acc[8*j+4], acc[8*j+5]);
        w.w = pack2h(acc[8*j+6], acc[8*j+7]);
        *(uint4*)(db + swz128((uint32_t)tid * 128 + j * 16)) = w;
    }
}

// ---------------------------------------------------------------------------
// Channel LayerNorm over C=512, fp16 in -> fp32 out (single pass, reg cache)
// ---------------------------------------------------------------------------
__global__ __launch_bounds__(256) void ln_kernel(
    const __half* __restrict__ in, float* __restrict__ out,
    const float* __restrict__ g, const float* __restrict__ be)
{
    __shared__ float ss[8][32], sq[8][32], smean[32], srstd[32];
    int blk = blockIdx.x;
    int b = blk >> 7;
    int li = threadIdx.x & 31;
    int l = ((blk & 127) << 5) + li;
    int r = threadIdx.x >> 5;
    const __half* base = in + (size_t)b * Cc * Ln + l;

    float s = 0.f, s2 = 0.f;
    float x0[64];
    #pragma unroll
    for (int k2 = 0; k2 < 64; k2++) {
        int c = r * 64 + k2;
        float x = __half2float(base[(size_t)c * Ln]);
        x0[k2] = x;
        s += x; s2 += x * x;
    }
    ss[r][li] = s; sq[r][li] = s2;
    __syncthreads();
    if (r == 0) {
        float ts = ss[0][li], t2 = sq[0][li];
        #pragma unroll
        for (int rr = 1; rr < 8; rr++) { ts += ss[rr][li]; t2 += sq[rr][li]; }
        float mean = ts * (1.f / 512.f);
        float var = t2 * (1.f / 512.f) - mean * mean;
        smean[li] = mean;
        srstd[li] = rsqrtf(var + 1e-5f);
    }
    __syncthreads();
    float mean = smean[li], rstd = srstd[li];
    float* ob = out + (size_t)b * Cc * Ln + l;
    #pragma unroll
    for (int k2 = 0; k2 < 64; k2++) {
        int c = r * 64 + k2;
        ob[(size_t)c * Ln] = (x0[k2] - mean) * rstd * g[c] + be[c];
    }
}

// ---------------------------------------------------------------------------
// Channel LayerNorm, fp16 in -> fp16 tiled out
// ---------------------------------------------------------------------------
__global__ __launch_bounds__(256) void ln_h(
    const __half* __restrict__ in, __half* __restrict__ outc,
    const float* __restrict__ g, const float* __restrict__ be)
{
    __shared__ float ss[8][32], sq[8][32], smean[32], srstd[32];
    int blk = blockIdx.x;
    int b = blk >> 7;
    int li = threadIdx.x & 31;
    int l = ((blk & 127) << 5) + li;
    int r = threadIdx.x >> 5;
    const __half* base = in + (size_t)b * Cc * Ln + l;

    float s = 0.f, s2 = 0.f;
    float x0[64];
    #pragma unroll
    for (int k2 = 0; k2 < 64; k2++) {
        int c = r * 64 + k2;
        float x = __half2float(base[(size_t)c * Ln]);
        x0[k2] = x;
        s += x; s2 += x * x;
    }
    ss[r][li] = s; sq[r][li] = s2;
    __syncthreads();
    if (r == 0) {
        float ts = ss[0][li], t2 = sq[0][li];
        #pragma unroll
        for (int rr = 1; rr < 8; rr++) { ts += ss[rr][li]; t2 += sq[rr][li]; }
        float mean = ts * (1.f / 512.f);
        float var = t2 * (1.f / 512.f) - mean * mean;
        smean[li] = mean;
        srstd[li] = rsqrtf(var + 1e-5f);
    }
    __syncthreads();
    float mean = smean[li], rstd = srstd[li];

    char* db = (char*)(outc + (((size_t)b * 16 + (l >> 8)) * 8 + r) * 16384);
    uint32_t row = (uint32_t)(l & 255);
    #pragma unroll
    for (int j = 0; j < 8; j++) {
        float v[8];
        #pragma unroll
        for (int q2 = 0; q2 < 8; q2++) {
            int c = r * 64 + j * 8 + q2;
            v[q2] = (x0[j * 8 + q2] - mean) * rstd * g[c] + be[c];
        }
        uint4 w;
        w.x = pack2h(v[0], v[1]);
        w.y = pack2h(v[2], v[3]);
        w.z = pack2h(v[4], v[5]);
        w.w = pack2h(v[6], v[7]);
        *(uint4*)(db + swz128(row * 128 + j * 16)) = w;
    }
}

// ---------------------------------------------------------------------------
extern "C" void kernel_launch(void* const* d_in, const int* in_sizes, int n_in,
                              void* d_out, int out_size)
{
    const float* z1  = (const float*)d_in[0];
    const float* z2  = (const float*)d_in[1];
    const float* Wq  = (const float*)d_in[2];
    const float* bq  = (const float*)d_in[3];
    const float* Wk  = (const float*)d_in[4];
    const float* bkb = (const float*)d_in[5];
    const float* Wv  = (const float*)d_in[6];
    const float* bv  = (const float*)d_in[7];
    const float* Wr  = (const float*)d_in[8];
    const float* br  = (const float*)d_in[9];
    const float* g1  = (const float*)d_in[10];
    const float* be1 = (const float*)d_in[11];
    const float* W1  = (const float*)d_in[12];
    const float* b1  = (const float*)d_in[13];
    const float* W2  = (const float*)d_in[14];
    const float* b2  = (const float*)d_in[15];
    const float* g2  = (const float*)d_in[16];
    const float* be2 = (const float*)d_in[17];

    float* fs = nullptr;
    cudaGetSymbolAddress((void**)&fs, g_scratch);
    __half* hf = nullptr;
    cudaGetSymbolAddress((void**)&hf, g_hf);

    const size_t SZ = (size_t)Bn * Cc * Ln;   // 16777216
    __half* qh  = (__half*)(fs);
    __half* kh  = (__half*)(fs + SZ);
    __half* vh  = (__half*)(fs + 2 * SZ);
    __half* zh  = (__half*)(fs + 4 * SZ);
    __half* yh  = (__half*)(fs + 5 * SZ);
    float* ctxp = fs + 6 * SZ;                 // NSPLIT*64*64*64 floats
    float* zp   = fs + 6 * SZ + 4194304;       // NSPLIT*64*64 floats
    float* ctxn = fs + 6 * SZ + 4325376;       // 64*4096 floats

    cudaFuncSetAttribute(gemm_wm, cudaFuncAttributeMaxDynamicSharedMemorySize, GEMM_SMEM);
    cudaFuncSetAttribute(gemm_qkv, cudaFuncAttributeMaxDynamicSharedMemorySize, GEMM_SMEM);

    dim3 thr(256);
    conv_w_all<<<dim3(16, 8, 6), thr>>>(Wq, Wk, Wv, Wr, W1, W2, hf);
    conv_x2<<<dim3(8, 16, 16), thr>>>(z1, z2, hf + OFF_Z1C, hf + OFF_Z2C);

    // Merged Q/K/V projections (all fp16 flat)
    gemm_qkv<<<dim3(4, 32, 24), thr, GEMM_SMEM>>>(hf, bq, bkb, bv, qh, kh, vh);

    // Attention core: ctx on tensor cores, one-shot reduce, scalar apply
    ctx_mma<<<dim3(Bn * Hh, NSPLIT), thr>>>(kh, vh, ctxp, zp);
    ctx_reduce<<<Bn * Hh, thr>>>(ctxp, zp, ctxn);
    att_fused<<<dim3(Ln / 256, Bn * Hh), thr>>>(ctxn, qh, hf + OFF_ATTC);

    // Reprojection + residual -> fp16 flat z
    gemm_wm<<<dim3(4, 32, 8), thr, GEMM_SMEM>>>(hf + OFF_WR, br, hf + OFF_ATTC, nullptr, zh, z1, 512, 512, 0, 2);

    // LN1 (fp16 in) -> fp16 tiled
    ln_h<<<Bn * (Ln / 32), thr>>>(zh, hf + OFF_ZC, g1, be1);

    // FFN1 -> fp16 tiled h (ELU fused), FFN2 -> fp16 flat y
    gemm_wm<<<dim3(8, 32, 8), thr, GEMM_SMEM>>>(hf + OFF_W1, b1, hf + OFF_ZC, nullptr, hf + OFF_HC, nullptr, 1024, 512, 1, 1);
    gemm_wm<<<dim3(4, 32, 8), thr, GEMM_SMEM>>>(hf + OFF_W2, b2, hf + OFF_HC, nullptr, yh, nullptr, 512, 1024, 0, 2);

    // LN2 (fp16 in) -> fp32 output
    ln_kernel<<<Bn * (Ln / 32), thr>>>(yh, (float*)d_out, g2, be2);
}

// round 16
// speedup vs baseline: 1.0551x; 1.0441x over previous
#include <cuda_runtime.h>
#include <cuda_fp16.h>
#include <cstdint>

// Problem constants
#define Bn  8
#define Cc  512
#define Ln  4096
#define Hh  8
#define Dh  64
#define NSPLIT 8

// ---------------------------------------------------------------------------
// Scratch
// ---------------------------------------------------------------------------
__device__ float g_scratch[135266304];
__device__ __half g_hf[102760448];

// half-element offsets into g_hf
#define OFF_Z1C  0ull
#define OFF_Z2C  16777216ull
#define OFF_ATTC 33554432ull
#define OFF_ZC   50331648ull
#define OFF_HC   67108864ull
#define OFF_WQ   100663296ull
#define OFF_WK   100925440ull
#define OFF_WV   101187584ull
#define OFF_WR   101449728ull
#define OFF_W1   101711872ull
#define OFF_W2   102236160ull

// ---------------------------------------------------------------------------
// Helpers
// ---------------------------------------------------------------------------
__device__ __forceinline__ uint32_t smem_u32(const void* p) {
    uint32_t a;
    asm("{ .reg .u64 t; cvta.to.shared.u64 t, %1; cvt.u32.u64 %0, t; }"
        : "=r"(a) : "l"(p));
    return a;
}
__device__ __host__ __forceinline__ uint32_t swz128(uint32_t off) {
    return off ^ ((off >> 3) & 0x70);
}
__device__ __forceinline__ void cpasync16(uint32_t d, const void* s) {
    asm volatile("cp.async.cg.shared.global [%0], [%1], 16;" :: "r"(d), "l"(s));
}
#define CP_COMMIT() asm volatile("cp.async.commit_group;" ::: "memory")
#define CP_WAIT(N)  asm volatile("cp.async.wait_group " #N ";" ::: "memory")

#define LDSM4(R, ADDR) \
    asm volatile("ldmatrix.sync.aligned.m8n8.x4.shared.b16 {%0,%1,%2,%3}, [%4];" \
        : "=r"((R)[0]), "=r"((R)[1]), "=r"((R)[2]), "=r"((R)[3]) : "r"(ADDR))

#define MMA16816(C, A, Bv) \
    asm volatile("mma.sync.aligned.m16n8k16.row.col.f32.f16.f16.f32 " \
        "{%0,%1,%2,%3}, {%4,%5,%6,%7}, {%8,%9}, {%0,%1,%2,%3};" \
        : "+f"((C)[0]), "+f"((C)[1]), "+f"((C)[2]), "+f"((C)[3]) \
        : "r"((A)[0]), "r"((A)[1]), "r"((A)[2]), "r"((A)[3]), \
          "r"((Bv)[0]), "r"((Bv)[1]))

__device__ __forceinline__ uint32_t pack2h(float a, float b) {
    __half2 h = __floats2half2_rn(a, b);
    return *(uint32_t*)&h;
}
__device__ __forceinline__ float elu_fast(float v) {
    return v > 0.f ? v : (__expf(v) - 1.f);
}

#define STG 32768u
#define GEMM_SMEM 98304   // 3 stages

// ---------------------------------------------------------------------------
// ALL conversions in one launch.
// grid (16, 16, 22): z<6 -> weight widx=z; z>=6 -> input conv, zz=z-6:
//   b=zz&7, which=zz>>3, kc=blockIdx.x(<8), lt=blockIdx.y(16)
// ---------------------------------------------------------------------------
__global__ __launch_bounds__(256) void conv_all(
    const float* __restrict__ Wq, const float* __restrict__ Wk,
    const float* __restrict__ Wv, const float* __restrict__ Wr,
    const float* __restrict__ W1, const float* __restrict__ W2,
    const float* __restrict__ z1, const float* __restrict__ z2,
    __half* __restrict__ hf)
{
    __shared__ float sm[32][264];
    int t = threadIdx.x;

    if (blockIdx.z < 6) {
        int widx = blockIdx.z;
        const float* src;
        __half* dstb;
        int K, MT;
        switch (widx) {
            case 0: src = Wq; dstb = hf + OFF_WQ; K = 512;  MT = 4; break;
            case 1: src = Wk; dstb = hf + OFF_WK; K = 512;  MT = 4; break;
            case 2: src = Wv; dstb = hf + OFF_WV; K = 512;  MT = 4; break;
            case 3: src = Wr; dstb = hf + OFF_WR; K = 512;  MT = 4; break;
            case 4: src = W1; dstb = hf + OFF_W1; K = 512;  MT = 8; break;
            default: src = W2; dstb = hf + OFF_W2; K = 1024; MT = 4; break;
        }
        int NC = K >> 6;
        int kc = blockIdx.x, mt = blockIdx.y;
        if (kc >= NC || mt >= MT) return;
        char* db = (char*)(dstb + ((size_t)(mt * NC + kc)) * 8192);
        const float* sb = src + ((size_t)mt * 128) * K + kc * 64;
        for (int it = 0; it < 4; it++) {
            int u = t + 256 * it;
            int r = u >> 3, g = u & 7;
            float x0[8];
            #pragma unroll
            for (int q = 0; q < 2; q++) {
                float4 v = *(const float4*)(sb + (size_t)r * K + g * 8 + q * 4);
                x0[q*4+0]=v.x; x0[q*4+1]=v.y; x0[q*4+2]=v.z; x0[q*4+3]=v.w;
            }
            uint4 w;
            w.x = pack2h(x0[0], x0[1]);
            w.y = pack2h(x0[2], x0[3]);
            w.z = pack2h(x0[4], x0[5]);
            w.w = pack2h(x0[6], x0[7]);
            uint32_t sw = swz128((uint32_t)r * 128 + g * 16);
            *(uint4*)(db + sw) = w;
        }
        return;
    }

    // input conversion
    const int K = 512;
    int zz = blockIdx.z - 6;
    int kc = blockIdx.x, lt = blockIdx.y;
    if (kc >= 8) return;
    int b = zz & 7;
    const float* src = (zz < 8) ? z1 : z2;
    __half* dstb = (zz < 8) ? (hf + OFF_Z1C) : (hf + OFF_Z2C);
    int NC = K >> 6;
    const float* sb = src + ((size_t)b * K + kc * 64) * Ln + (size_t)lt * 256;
    char* db = (char*)(dstb + (((size_t)b * 16 + lt) * NC + kc) * 16384);
    for (int p = 0; p < 2; p++) {
        __syncthreads();
        #pragma unroll
        for (int i = 0; i < 8; i++) {
            int u = t + 256 * i;
            int kr = u >> 6;
            int lc = u & 63;
            float4 v = *(const float4*)(sb + ((size_t)(p * 32 + kr)) * Ln + lc * 4);
            sm[kr][lc*4+0]=v.x; sm[kr][lc*4+1]=v.y; sm[kr][lc*4+2]=v.z; sm[kr][lc*4+3]=v.w;
        }
        __syncthreads();
        #pragma unroll
        for (int g = 0; g < 4; g++) {
            float x0[8];
            #pragma unroll
            for (int j = 0; j < 8; j++) x0[j] = sm[g*8+j][t];
            uint4 w;
            w.x = pack2h(x0[0], x0[1]);
            w.y = pack2h(x0[2], x0[3]);
            w.z = pack2h(x0[4], x0[5]);
            w.w = pack2h(x0[6], x0[7]);
            uint32_t sw = swz128((uint32_t)t * 128 + (p * 32 + g * 8) * 2);
            *(uint4*)(db + sw) = w;
        }
    }
}

// ---------------------------------------------------------------------------
// Shared GEMM mainloop (256 threads, 8 warps 64x32, 128x128 tile, 3 stages)
// ---------------------------------------------------------------------------
#define GEMM_PROLOGUE() \
    uint32_t sbase = smem_u32(smem); \
    int tid = threadIdx.x, wid = tid >> 5, lane = tid & 31; \
    int wm = wid >> 2, wn = wid & 3; \
    int sub = lane >> 3, r = lane & 7; \
    uint32_t aRow[4], aMask[4]; \
    int kaddA = (sub >> 1) * 16; \
    _Pragma("unroll") \
    for (int i = 0; i < 4; i++) { \
        uint32_t row = wm * 64 + i * 16 + (sub & 1) * 8 + r; \
        aRow[i] = row * 128; \
        aMask[i] = (aRow[i] >> 3) & 0x70; \
    } \
    uint32_t bRow[2], bMask[2]; \
    int kaddB = (sub & 1) * 16; \
    _Pragma("unroll") \
    for (int j = 0; j < 2; j++) { \
        uint32_t row = wn * 32 + j * 16 + (sub >> 1) * 8 + r; \
        bRow[j] = row * 128; \
        bMask[j] = (bRow[j] >> 3) & 0x70; \
    } \
    float acc[4][4][4]; \
    _Pragma("unroll") \
    for (int i = 0; i < 4; i++) \
        _Pragma("unroll") \
        for (int j = 0; j < 4; j++) \
            _Pragma("unroll") \
            for (int q = 0; q < 4; q++) acc[i][j][q] = 0.f;

#define GEMM_LOAD_STAGE(kc, s) do { \
    uint32_t S = sbase + (uint32_t)(s) * STG; \
    const char* ah = Abase + (size_t)(kc) * 16384; \
    const char* bh = Bbase + (size_t)(kc) * 32768; \
    _Pragma("unroll") \
    for (int q = 0; q < 4; q++) { \
        uint32_t off = (uint32_t)tid * 64 + q * 16; \
        cpasync16(S + off,         ah + off); \
        cpasync16(S + 16384 + off, bh + off); \
    } \
} while (0)

#define GEMM_MAINLOOP(NC) \
    GEMM_LOAD_STAGE(0, 0); CP_COMMIT(); \
    if ((NC) > 1) { GEMM_LOAD_STAGE(1, 1); CP_COMMIT(); } \
    int sc = 0; \
    for (int c = 0; c < (NC); c++) { \
        CP_WAIT(1); \
        __syncthreads(); \
        if (c + 2 < (NC)) { \
            int s2 = sc + 2; if (s2 >= 3) s2 -= 3; \
            GEMM_LOAD_STAGE(c + 2, s2); CP_COMMIT(); \
        } \
        uint32_t S = sbase + (uint32_t)sc * STG; \
        _Pragma("unroll") \
        for (int kk = 0; kk < 4; kk++) { \
            int kb = kk * 32; \
            uint32_t aa[16], bb[8]; \
            _Pragma("unroll") \
            for (int i = 0; i < 4; i++) \
                LDSM4(&aa[i * 4], S + aRow[i] + (uint32_t)((kaddA + kb) ^ aMask[i])); \
            _Pragma("unroll") \
            for (int j = 0; j < 2; j++) \
                LDSM4(&bb[j * 4], S + 16384 + bRow[j] + (uint32_t)((kaddB + kb) ^ bMask[j])); \
            _Pragma("unroll") \
            for (int mi = 0; mi < 4; mi++) \
                _Pragma("unroll") \
                for (int nj = 0; nj < 4; nj++) \
                    MMA16816(acc[mi][nj], &aa[mi * 4], &bb[nj * 2]); \
        } \
        sc++; if (sc == 3) sc = 0; \
    }

// ---------------------------------------------------------------------------
// Merged Q/K/V projection GEMM: grid (4, 32, 24); z>>3 selects {Q,K,V}.
// All outputs fp16 flat [B, C, L].
// ---------------------------------------------------------------------------
__global__ __launch_bounds__(256, 2) void gemm_qkv(
    const __half* __restrict__ hf,
    const float* __restrict__ bq, const float* __restrict__ bk,
    const float* __restrict__ bv,
    __half* __restrict__ qh, __half* __restrict__ kh, __half* __restrict__ vh)
{
    extern __shared__ __align__(1024) char smem[];
    const int NC = 8;
    int mt = blockIdx.x, lt = blockIdx.y;
    int which = blockIdx.z >> 3, b = blockIdx.z & 7;

    const __half* Wc = (which == 0) ? hf + OFF_WQ : (which == 1) ? hf + OFF_WK : hf + OFF_WV;
    const float* bias = (which == 0) ? bq : (which == 1) ? bk : bv;
    const __half* Xc = (which == 0) ? hf + OFF_Z1C : hf + OFF_Z2C;
    __half* Out = (which == 0) ? qh : (which == 1) ? kh : vh;

    const char* Abase = (const char*)Wc + ((size_t)mt * NC) * 16384;
    int lt256 = lt >> 1, half = lt & 1;
    const char* Bbase = (const char*)Xc + (((size_t)b * 16 + lt256) * NC) * 32768
                        + (size_t)half * 16384;

    GEMM_PROLOGUE();
    GEMM_MAINLOOP(NC);

    int g = lane >> 2, tg = lane & 3;
    #pragma unroll
    for (int mi = 0; mi < 4; mi++) {
        #pragma unroll
        for (int h2 = 0; h2 < 2; h2++) {
            int m = mt * 128 + wm * 64 + mi * 16 + h2 * 8 + g;
            float bi = bias[m];
            size_t rowoff = ((size_t)b * 512 + m) * Ln + (size_t)lt * 128 + wn * 32;
            #pragma unroll
            for (int nj = 0; nj < 4; nj++) {
                int col = nj * 8 + 2 * tg;
                float v0 = acc[mi][nj][h2 * 2 + 0] + bi;
                float v1 = acc[mi][nj][h2 * 2 + 1] + bi;
                *(__half2*)(Out + rowoff + col) = __floats2half2_rn(v0, v1);
            }
        }
    }
}

// ---------------------------------------------------------------------------
// General GEMM. outmode 0: fp32 Out (+Res)(+ELU). outmode 1: fp16 tiled Outh.
// outmode 2: fp16 flat Outh (+Res fp32)(+ELU).
// ---------------------------------------------------------------------------
__global__ __launch_bounds__(256, 2) void gemm_wm(
    const __half* __restrict__ Wc, const float* __restrict__ bias,
    const __half* __restrict__ Xc, float* __restrict__ Out,
    __half* __restrict__ Outh,
    const float* __restrict__ Res, int M, int K, int act, int outmode)
{
    extern __shared__ __align__(1024) char smem[];
    const int NC = K >> 6;
    int mt = blockIdx.x, lt = blockIdx.y, b = blockIdx.z;

    const char* Abase = (const char*)Wc + ((size_t)mt * NC) * 16384;
    int lt256 = lt >> 1, half = lt & 1;
    const char* Bbase = (const char*)Xc + (((size_t)b * 16 + lt256) * NC) * 32768
                        + (size_t)half * 16384;

    GEMM_PROLOGUE();
    GEMM_MAINLOOP(NC);

    int g = lane >> 2, tg = lane & 3;

    if (outmode == 0) {
        #pragma unroll
        for (int mi = 0; mi < 4; mi++) {
            #pragma unroll
            for (int h2 = 0; h2 < 2; h2++) {
                int m = mt * 128 + wm * 64 + mi * 16 + h2 * 8 + g;
                float bi = bias[m];
                size_t rowoff = ((size_t)b * M + m) * Ln + (size_t)lt * 128 + wn * 32;
                #pragma unroll
                for (int nj = 0; nj < 4; nj++) {
                    int col = nj * 8 + 2 * tg;
                    float v0 = acc[mi][nj][h2 * 2 + 0] + bi;
                    float v1 = acc[mi][nj][h2 * 2 + 1] + bi;
                    if (Res) {
                        float2 r2 = *(const float2*)(Res + rowoff + col);
                        v0 += r2.x; v1 += r2.y;
                    }
                    if (act) { v0 = elu_fast(v0); v1 = elu_fast(v1); }
                    *(float2*)(Out + rowoff + col) = make_float2(v0, v1);
                }
            }
        }
    } else if (outmode == 2) {
        #pragma unroll
        for (int mi = 0; mi < 4; mi++) {
            #pragma unroll
            for (int h2 = 0; h2 < 2; h2++) {
                int m = mt * 128 + wm * 64 + mi * 16 + h2 * 8 + g;
                float bi = bias[m];
                size_t rowoff = ((size_t)b * M + m) * Ln + (size_t)lt * 128 + wn * 32;
                #pragma unroll
                for (int nj = 0; nj < 4; nj++) {
                    int col = nj * 8 + 2 * tg;
                    float v0 = acc[mi][nj][h2 * 2 + 0] + bi;
                    float v1 = acc[mi][nj][h2 * 2 + 1] + bi;
                    if (Res) {
                        float2 r2 = *(const float2*)(Res + rowoff + col);
                        v0 += r2.x; v1 += r2.y;
                    }
                    if (act) { v0 = elu_fast(v0); v1 = elu_fast(v1); }
                    *(__half2*)(Outh + rowoff + col) = __floats2half2_rn(v0, v1);
                }
            }
        }
    } else {
        __syncthreads();
        __half* smh = (__half*)smem;
        #pragma unroll
        for (int mi = 0; mi < 4; mi++) {
            #pragma unroll
            for (int h2 = 0; h2 < 2; h2++) {
                int ml = wm * 64 + mi * 16 + h2 * 8 + g;
                float bi = bias[mt * 128 + ml];
                #pragma unroll
                for (int nj = 0; nj < 4; nj++) {
                    int ll = wn * 32 + nj * 8 + 2 * tg;
                    float v0 = acc[mi][nj][h2 * 2 + 0] + bi;
                    float v1 = acc[mi][nj][h2 * 2 + 1] + bi;
                    if (act) { v0 = elu_fast(v0); v1 = elu_fast(v1); }
                    smh[(uint32_t)ll * 136 + ml]       = __float2half(v0);
                    smh[(uint32_t)(ll + 1) * 136 + ml] = __float2half(v1);
                }
            }
        }
        __syncthreads();
        int rowbase = (lt & 1) * 128;
        int NCo = M >> 6;
        #pragma unroll
        for (int kc = 0; kc < 2; kc++) {
            char* db = (char*)(Outh + (((size_t)b * 16 + lt256) * NCo + (mt * 2 + kc)) * 16384);
            #pragma unroll
            for (int it = 0; it < 4; it++) {
                int u = tid + 256 * it;
                int row = u >> 3, j = u & 7;
                uint4 w = *(uint4*)&smh[(uint32_t)row * 136 + kc * 64 + j * 8];
                *(uint4*)(db + swz128((uint32_t)(rowbase + row) * 128 + j * 16)) = w;
            }
        }
    }
}

// ---------------------------------------------------------------------------
// ctx via tensor cores (exp folded), double-buffered, one sync/chunk.
// grid (64, NSPLIT), 256 threads.
// ---------------------------------------------------------------------------
__global__ __launch_bounds__(256) void ctx_mma(
    const __half* __restrict__ kk, const __half* __restrict__ vv,
    float* __restrict__ ctxp, float* __restrict__ zp)
{
    __shared__ __align__(1024) char smem[32768];
    uint32_t sb = smem_u32(smem);
    int bh = blockIdx.x, sp = blockIdx.y;
    int tid = threadIdx.x, wid = tid >> 5, lane = tid & 31;
    const __half* kb = kk + (size_t)bh * Dh * Ln;
    const __half* vb = vv + (size_t)bh * Dh * Ln;

    int lrow = tid >> 2;
    int lu = (tid & 3) * 2;
    uint32_t sw0 = swz128((uint32_t)lrow * 128 + lu * 16);
    uint32_t sw1 = swz128((uint32_t)lrow * 128 + lu * 16 + 16);

    int mtile = wid >> 1;
    int ntile = (wid & 1) * 32;
    int sub = lane >> 3, r7 = lane & 7;
    uint32_t aRowOff = (uint32_t)(mtile * 16 + (sub & 1) * 8 + r7) * 128;
    uint32_t aMask = (aRowOff >> 3) & 0x70;
    int kaddA = (sub >> 1) * 16;
    uint32_t bRowOff[2], bMask[2];
    int kaddB = (sub & 1) * 16;
    #pragma unroll
    for (int j = 0; j < 2; j++) {
        uint32_t row = (uint32_t)(ntile + j * 16 + (sub >> 1) * 8 + r7);
        bRowOff[j] = row * 128;
        bMask[j] = (bRowOff[j] >> 3) & 0x70;
    }

    float acc[4][4];
    #pragma unroll
    for (int i = 0; i < 4; i++)
        #pragma unroll
        for (int j = 0; j < 4; j++) acc[i][j] = 0.f;
    float zacc = 0.f;

    int lbeg = sp * (Ln / NSPLIT);
    const int NCH = (Ln / NSPLIT) / 64;   // 8
    for (int ch = 0; ch < NCH; ch++) {
        int l0 = lbeg + ch * 64;
        uint32_t buf = (uint32_t)(ch & 1) * 16384;
        const __half* kr = kb + (size_t)lrow * Ln + l0 + lu * 8;
        const __half* vr = vb + (size_t)lrow * Ln + l0 + lu * 8;
        uint4 k0 = *(const uint4*)kr;
        uint4 k1 = *(const uint4*)(kr + 8);
        uint4 v0 = *(const uint4*)vr;
        uint4 v1 = *(const uint4*)(vr + 8);
        uint32_t* kw;
        kw = (uint32_t*)&k0;
        #pragma unroll
        for (int i = 0; i < 4; i++) {
            float2 f = __half22float2(*(__half2*)&kw[i]);
            f.x = __expf(f.x); f.y = __expf(f.y);
            zacc += f.x + f.y;
            kw[i] = pack2h(f.x, f.y);
        }
        kw = (uint32_t*)&k1;
        #pragma unroll
        for (int i = 0; i < 4; i++) {
            float2 f = __half22float2(*(__half2*)&kw[i]);
            f.x = __expf(f.x); f.y = __expf(f.y);
            zacc += f.x + f.y;
            kw[i] = pack2h(f.x, f.y);
        }
        *(uint4*)(smem + buf + sw0) = k0;
        *(uint4*)(smem + buf + sw1) = k1;
        *(uint4*)(smem + buf + 8192 + sw0) = v0;
        *(uint4*)(smem + buf + 8192 + sw1) = v1;
        __syncthreads();
        #pragma unroll
        for (int kk2 = 0; kk2 < 4; kk2++) {
            int kbyte = kk2 * 32;
            uint32_t aa[4], bbv[8];
            LDSM4(aa, sb + buf + aRowOff + (uint32_t)((kaddA + kbyte) ^ aMask));
            #pragma unroll
            for (int j = 0; j < 2; j++)
                LDSM4(&bbv[j * 4], sb + buf + 8192 + bRowOff[j] + (uint32_t)((kaddB + kbyte) ^ bMask[j]));
            #pragma unroll
            for (int nj = 0; nj < 4; nj++)
                MMA16816(acc[nj], aa, &bbv[nj * 2]);
        }
    }

    int g = lane >> 2, tg = lane & 3;
    float* cbase = ctxp + ((size_t)sp * 64 + bh) * 4096;
    #pragma unroll
    for (int nj = 0; nj < 4; nj++) {
        int dv = ntile + nj * 8 + 2 * tg;
        int dk0 = mtile * 16 + g;
        *(float2*)(cbase + (size_t)dk0 * 64 + dv)       = make_float2(acc[nj][0], acc[nj][1]);
        *(float2*)(cbase + (size_t)(dk0 + 8) * 64 + dv) = make_float2(acc[nj][2], acc[nj][3]);
    }
    zacc += __shfl_xor_sync(0xFFFFFFFFu, zacc, 1);
    zacc += __shfl_xor_sync(0xFFFFFFFFu, zacc, 2);
    if ((tid & 3) == 0)
        zp[((size_t)sp * 64 + bh) * 64 + lrow] = zacc;
}

// ---------------------------------------------------------------------------
// ctx_reduce: reduce NSPLIT partials + Z-normalize ONCE -> fp32 ctxn
// ---------------------------------------------------------------------------
__global__ __launch_bounds__(256) void ctx_reduce(
    const float* __restrict__ ctxp, const float* __restrict__ zp,
    float* __restrict__ ctxn)
{
    int bh = blockIdx.x;
    __shared__ float zinv[64];
    int tid = threadIdx.x;

    if (tid < 64) {
        float zs = 0.f;
        #pragma unroll
        for (int s = 0; s < NSPLIT; s++)
            zs += zp[((size_t)s * 64 + bh) * 64 + tid];
        zinv[tid] = 1.f / zs;
    }
    __syncthreads();

    float4* ob = (float4*)(ctxn + (size_t)bh * 4096);
    #pragma unroll
    for (int r = 0; r < 4; r++) {
        int idx = tid + 256 * r;
        float zi = zinv[idx >> 4];
        float4 sum = make_float4(0.f, 0.f, 0.f, 0.f);
        #pragma unroll
        for (int s = 0; s < NSPLIT; s++) {
            const float4* p = (const float4*)(ctxp + ((size_t)s * 64 + bh) * 4096);
            float4 t = p[idx];
            sum.x += t.x; sum.y += t.y; sum.z += t.z; sum.w += t.w;
        }
        sum.x *= zi; sum.y *= zi; sum.z *= zi; sum.w *= zi;
        ob[idx] = sum;
    }
}

// ---------------------------------------------------------------------------
// att fused: load normalized ctx once, head-softmax(q fp16) inline with
// fp16-packed weights, fp16 tiled output. grid (16, 64), 256 threads.
// ---------------------------------------------------------------------------
__global__ __launch_bounds__(256) void att_fused(
    const float* __restrict__ ctxn, const __half* __restrict__ qh,
    __half* __restrict__ attc)
{
    int bh = blockIdx.y;
    int b = bh >> 3, h = bh & 7;
    __shared__ float cs[64][64];
    int tid = threadIdx.x;

    float4* cs4 = (float4*)cs;
    const float4* p = (const float4*)(ctxn + (size_t)bh * 4096);
    #pragma unroll
    for (int r = 0; r < 4; r++) {
        int idx = tid + 256 * r;
        cs4[idx] = p[idx];
    }
    __syncthreads();

    int l = blockIdx.x * 256 + tid;
    const __half* qb = qh + (size_t)bh * Dh * Ln + l;

    uint32_t qp[32];
    {
        float qv[64];
        float mx = -1e30f;
        #pragma unroll
        for (int d = 0; d < 64; d++) {
            qv[d] = __half2float(qb[(size_t)d * Ln]);
            mx = fmaxf(mx, qv[d]);
        }
        float s = 0.f;
        #pragma unroll
        for (int d = 0; d < 64; d++) { qv[d] = __expf(qv[d] - mx); s += qv[d]; }
        float inv = 1.f / s;
        #pragma unroll
        for (int dp = 0; dp < 32; dp++)
            qp[dp] = pack2h(qv[2 * dp] * inv, qv[2 * dp + 1] * inv);
    }

    float acc[64];
    #pragma unroll
    for (int d = 0; d < 64; d++) acc[d] = 0.f;

    #pragma unroll 4
    for (int dp = 0; dp < 32; dp++) {
        float2 qq = __half22float2(*(__half2*)&qp[dp]);
        int dk0 = 2 * dp;
        #pragma unroll
        for (int j = 0; j < 16; j++) {
            float4 c0 = *(const float4*)&cs[dk0][j * 4];
            float4 c1 = *(const float4*)&cs[dk0 + 1][j * 4];
            acc[4 * j + 0] += c0.x * qq.x + c1.x * qq.y;
            acc[4 * j + 1] += c0.y * qq.x + c1.y * qq.y;
            acc[4 * j + 2] += c0.z * qq.x + c1.z * qq.y;
            acc[4 * j + 3] += c0.w * qq.x + c1.w * qq.y;
        }
    }

    char* db = (char*)(attc + (((size_t)b * 16 + blockIdx.x) * 8 + h) * 16384);
    #pragma unroll
    for (int j = 0; j < 8; j++) {
        uint4 w;
        w.x = pack2h(acc[8*j+0], acc[8*j+1]);
        w.y = pack2h(acc[8*j+2], acc[8*j+3]);
        w.z = pack2h(acc[8*j+4], acc[8*j+5]);
        w.w = pack2h(acc[8*j+6], acc[8*j+7]);
        *(uint4*)(db + swz128((uint32_t)tid * 128 + j * 16)) = w;
    }
}

// ---------------------------------------------------------------------------
// Channel LayerNorm over C=512, fp16 in -> fp32 out (single pass, reg cache)
// ---------------------------------------------------------------------------
__global__ __launch_bounds__(256) void ln_kernel(
    const __half* __restrict__ in, float* __restrict__ out,
    const float* __restrict__ g, const float* __restrict__ be)
{
    __shared__ float ss[8][32], sq[8][32], smean[32], srstd[32];
    int blk = blockIdx.x;
    int b = blk >> 7;
    int li = threadIdx.x & 31;
    int l = ((blk & 127) << 5) + li;
    int r = threadIdx.x >> 5;
    const __half* base = in + (size_t)b * Cc * Ln + l;

    float s = 0.f, s2 = 0.f;
    float x0[64];
    #pragma unroll
    for (int k2 = 0; k2 < 64; k2++) {
        int c = r * 64 + k2;
        float x = __half2float(base[(size_t)c * Ln]);
        x0[k2] = x;
        s += x; s2 += x * x;
    }
    ss[r][li] = s; sq[r][li] = s2;
    __syncthreads();
    if (r == 0) {
        float ts = ss[0][li], t2 = sq[0][li];
        #pragma unroll
        for (int rr = 1; rr < 8; rr++) { ts += ss[rr][li]; t2 += sq[rr][li]; }
        float mean = ts * (1.f / 512.f);
        float var = t2 * (1.f / 512.f) - mean * mean;
        smean[li] = mean;
        srstd[li] = rsqrtf(var + 1e-5f);
    }
    __syncthreads();
    float mean = smean[li], rstd = srstd[li];
    float* ob = out + (size_t)b * Cc * Ln + l;
    #pragma unroll
    for (int k2 = 0; k2 < 64; k2++) {
        int c = r * 64 + k2;
        ob[(size_t)c * Ln] = (x0[k2] - mean) * rstd * g[c] + be[c];
    }
}

// ---------------------------------------------------------------------------
// Channel LayerNorm, fp16 in -> fp16 tiled out
// ---------------------------------------------------------------------------
__global__ __launch_bounds__(256) void ln_h(
    const __half* __restrict__ in, __half* __restrict__ outc,
    const float* __restrict__ g, const float* __restrict__ be)
{
    __shared__ float ss[8][32], sq[8][32], smean[32], srstd[32];
    int blk = blockIdx.x;
    int b = blk >> 7;
    int li = threadIdx.x & 31;
    int l = ((blk & 127) << 5) + li;
    int r = threadIdx.x >> 5;
    const __half* base = in + (size_t)b * Cc * Ln + l;

    float s = 0.f, s2 = 0.f;
    float x0[64];
    #pragma unroll
    for (int k2 = 0; k2 < 64; k2++) {
        int c = r * 64 + k2;
        float x = __half2float(base[(size_t)c * Ln]);
        x0[k2] = x;
        s += x; s2 += x * x;
    }
    ss[r][li] = s; sq[r][li] = s2;
    __syncthreads();
    if (r == 0) {
        float ts = ss[0][li], t2 = sq[0][li];
        #pragma unroll
        for (int rr = 1; rr < 8; rr++) { ts += ss[rr][li]; t2 += sq[rr][li]; }
        float mean = ts * (1.f / 512.f);
        float var = t2 * (1.f / 512.f) - mean * mean;
        smean[li] = mean;
        srstd[li] = rsqrtf(var + 1e-5f);
    }
    __syncthreads();
    float mean = smean[li], rstd = srstd[li];

    char* db = (char*)(outc + (((size_t)b * 16 + (l >> 8)) * 8 + r) * 16384);
    uint32_t row = (uint32_t)(l & 255);
    #pragma unroll
    for (int j = 0; j < 8; j++) {
        float v[8];
        #pragma unroll
        for (int q2 = 0; q2 < 8; q2++) {
            int c = r * 64 + j * 8 + q2;
            v[q2] = (x0[j * 8 + q2] - mean) * rstd * g[c] + be[c];
        }
        uint4 w;
        w.x = pack2h(v[0], v[1]);
        w.y = pack2h(v[2], v[3]);
        w.z = pack2h(v[4], v[5]);
        w.w = pack2h(v[6], v[7]);
        *(uint4*)(db + swz128(row * 128 + j * 16)) = w;
    }
}

// ---------------------------------------------------------------------------
extern "C" void kernel_launch(void* const* d_in, const int* in_sizes, int n_in,
                              void* d_out, int out_size)
{
    const float* z1  = (const float*)d_in[0];
    const float* z2  = (const float*)d_in[1];
    const float* Wq  = (const float*)d_in[2];
    const float* bq  = (const float*)d_in[3];
    const float* Wk  = (const float*)d_in[4];
    const float* bkb = (const float*)d_in[5];
    const float* Wv  = (const float*)d_in[6];
    const float* bv  = (const float*)d_in[7];
    const float* Wr  = (const float*)d_in[8];
    const float* br  = (const float*)d_in[9];
    const float* g1  = (const float*)d_in[10];
    const float* be1 = (const float*)d_in[11];
    const float* W1  = (const float*)d_in[12];
    const float* b1  = (const float*)d_in[13];
    const float* W2  = (const float*)d_in[14];
    const float* b2  = (const float*)d_in[15];
    const float* g2  = (const float*)d_in[16];
    const float* be2 = (const float*)d_in[17];

    float* fs = nullptr;
    cudaGetSymbolAddress((void**)&fs, g_scratch);
    __half* hf = nullptr;
    cudaGetSymbolAddress((void**)&hf, g_hf);

    const size_t SZ = (size_t)Bn * Cc * Ln;   // 16777216
    __half* qh  = (__half*)(fs);
    __half* kh  = (__half*)(fs + SZ);
    __half* vh  = (__half*)(fs + 2 * SZ);
    __half* zh  = (__half*)(fs + 4 * SZ);
    __half* yh  = (__half*)(fs + 5 * SZ);
    float* ctxp = fs + 6 * SZ;                 // NSPLIT*64*64*64 floats
    float* zp   = fs + 6 * SZ + 4194304;       // NSPLIT*64*64 floats
    float* ctxn = fs + 6 * SZ + 4325376;       // 64*4096 floats

    cudaFuncSetAttribute(gemm_wm, cudaFuncAttributeMaxDynamicSharedMemorySize, GEMM_SMEM);
    cudaFuncSetAttribute(gemm_qkv, cudaFuncAttributeMaxDynamicSharedMemorySize, GEMM_SMEM);

    dim3 thr(256);
    // All conversions in one launch
    conv_all<<<dim3(16, 16, 22), thr>>>(Wq, Wk, Wv, Wr, W1, W2, z1, z2, hf);

    // Merged Q/K/V projections (all fp16 flat)
    gemm_qkv<<<dim3(4, 32, 24), thr, GEMM_SMEM>>>(hf, bq, bkb, bv, qh, kh, vh);

    // Attention core: ctx on tensor cores, one-shot reduce, scalar apply
    ctx_mma<<<dim3(Bn * Hh, NSPLIT), thr>>>(kh, vh, ctxp, zp);
    ctx_reduce<<<Bn * Hh, thr>>>(ctxp, zp, ctxn);
    att_fused<<<dim3(Ln / 256, Bn * Hh), thr>>>(ctxn, qh, hf + OFF_ATTC);

    // Reprojection + residual -> fp16 flat z
    gemm_wm<<<dim3(4, 32, 8), thr, GEMM_SMEM>>>(hf + OFF_WR, br, hf + OFF_ATTC, nullptr, zh, z1, 512, 512, 0, 2);

    // LN1 (fp16 in) -> fp16 tiled
    ln_h<<<Bn * (Ln / 32), thr>>>(zh, hf + OFF_ZC, g1, be1);

    // FFN1 -> fp16 tiled h (ELU fused), FFN2 -> fp16 flat y
    gemm_wm<<<dim3(8, 32, 8), thr, GEMM_SMEM>>>(hf + OFF_W1, b1, hf + OFF_ZC, nullptr, hf + OFF_HC, nullptr, 1024, 512, 1, 1);
    gemm_wm<<<dim3(4, 32, 8), thr, GEMM_SMEM>>>(hf + OFF_W2, b2, hf + OFF_HC, nullptr, yh, nullptr, 512, 1024, 0, 2);

    // LN2 (fp16 in) -> fp32 output
    ln_kernel<<<Bn * (Ln / 32), thr>>>(yh, (float*)d_out, g2, be2);
}

// round 17
// speedup vs baseline: 1.0575x; 1.0023x over previous
#include <cuda_runtime.h>
#include <cuda_fp16.h>
#include <cstdint>

// Problem constants
#define Bn  8
#define Cc  512
#define Ln  4096
#define Hh  8
#define Dh  64
#define NSPLIT 8

// ---------------------------------------------------------------------------
// Scratch
// ---------------------------------------------------------------------------
__device__ float g_scratch[135266304];
__device__ __half g_hf[102760448];

// half-element offsets into g_hf
#define OFF_Z1C  0ull
#define OFF_Z2C  16777216ull
#define OFF_ATTC 33554432ull
#define OFF_ZC   50331648ull
#define OFF_HC   67108864ull
#define OFF_WQ   100663296ull
#define OFF_WK   100925440ull
#define OFF_WV   101187584ull
#define OFF_WR   101449728ull
#define OFF_W1   101711872ull
#define OFF_W2   102236160ull

// ---------------------------------------------------------------------------
// Helpers
// ---------------------------------------------------------------------------
__device__ __forceinline__ uint32_t smem_u32(const void* p) {
    uint32_t a;
    asm("{ .reg .u64 t; cvta.to.shared.u64 t, %1; cvt.u32.u64 %0, t; }"
        : "=r"(a) : "l"(p));
    return a;
}
__device__ __host__ __forceinline__ uint32_t swz128(uint32_t off) {
    return off ^ ((off >> 3) & 0x70);
}
__device__ __forceinline__ void cpasync16(uint32_t d, const void* s) {
    asm volatile("cp.async.cg.shared.global [%0], [%1], 16;" :: "r"(d), "l"(s));
}
#define CP_COMMIT() asm volatile("cp.async.commit_group;" ::: "memory")
#define CP_WAIT(N)  asm volatile("cp.async.wait_group " #N ";" ::: "memory")

#define LDSM4(R, ADDR) \
    asm volatile("ldmatrix.sync.aligned.m8n8.x4.shared.b16 {%0,%1,%2,%3}, [%4];" \
        : "=r"((R)[0]), "=r"((R)[1]), "=r"((R)[2]), "=r"((R)[3]) : "r"(ADDR))

#define MMA16816(C, A, Bv) \
    asm volatile("mma.sync.aligned.m16n8k16.row.col.f32.f16.f16.f32 " \
        "{%0,%1,%2,%3}, {%4,%5,%6,%7}, {%8,%9}, {%0,%1,%2,%3};" \
        : "+f"((C)[0]), "+f"((C)[1]), "+f"((C)[2]), "+f"((C)[3]) \
        : "r"((A)[0]), "r"((A)[1]), "r"((A)[2]), "r"((A)[3]), \
          "r"((Bv)[0]), "r"((Bv)[1]))

__device__ __forceinline__ uint32_t pack2h(float a, float b) {
    __half2 h = __floats2half2_rn(a, b);
    return *(uint32_t*)&h;
}
__device__ __forceinline__ float elu_fast(float v) {
    return v > 0.f ? v : (__expf(v) - 1.f);
}

#define STG 32768u
#define GEMM_SMEM 98304   // 3 stages

// ---------------------------------------------------------------------------
// ALL conversions in one launch. grid (16, 16, 22)
// ---------------------------------------------------------------------------
__global__ __launch_bounds__(256) void conv_all(
    const float* __restrict__ Wq, const float* __restrict__ Wk,
    const float* __restrict__ Wv, const float* __restrict__ Wr,
    const float* __restrict__ W1, const float* __restrict__ W2,
    const float* __restrict__ z1, const float* __restrict__ z2,
    __half* __restrict__ hf)
{
    __shared__ float sm[32][264];
    int t = threadIdx.x;

    if (blockIdx.z < 6) {
        int widx = blockIdx.z;
        const float* src;
        __half* dstb;
        int K, MT;
        switch (widx) {
            case 0: src = Wq; dstb = hf + OFF_WQ; K = 512;  MT = 4; break;
            case 1: src = Wk; dstb = hf + OFF_WK; K = 512;  MT = 4; break;
            case 2: src = Wv; dstb = hf + OFF_WV; K = 512;  MT = 4; break;
            case 3: src = Wr; dstb = hf + OFF_WR; K = 512;  MT = 4; break;
            case 4: src = W1; dstb = hf + OFF_W1; K = 512;  MT = 8; break;
            default: src = W2; dstb = hf + OFF_W2; K = 1024; MT = 4; break;
        }
        int NC = K >> 6;
        int kc = blockIdx.x, mt = blockIdx.y;
        if (kc >= NC || mt >= MT) return;
        char* db = (char*)(dstb + ((size_t)(mt * NC + kc)) * 8192);
        const float* sb = src + ((size_t)mt * 128) * K + kc * 64;
        for (int it = 0; it < 4; it++) {
            int u = t + 256 * it;
            int r = u >> 3, g = u & 7;
            float x0[8];
            #pragma unroll
            for (int q = 0; q < 2; q++) {
                float4 v = *(const float4*)(sb + (size_t)r * K + g * 8 + q * 4);
                x0[q*4+0]=v.x; x0[q*4+1]=v.y; x0[q*4+2]=v.z; x0[q*4+3]=v.w;
            }
            uint4 w;
            w.x = pack2h(x0[0], x0[1]);
            w.y = pack2h(x0[2], x0[3]);
            w.z = pack2h(x0[4], x0[5]);
            w.w = pack2h(x0[6], x0[7]);
            uint32_t sw = swz128((uint32_t)r * 128 + g * 16);
            *(uint4*)(db + sw) = w;
        }
        return;
    }

    // input conversion
    const int K = 512;
    int zz = blockIdx.z - 6;
    int kc = blockIdx.x, lt = blockIdx.y;
    if (kc >= 8) return;
    int b = zz & 7;
    const float* src = (zz < 8) ? z1 : z2;
    __half* dstb = (zz < 8) ? (hf + OFF_Z1C) : (hf + OFF_Z2C);
    int NC = K >> 6;
    const float* sb = src + ((size_t)b * K + kc * 64) * Ln + (size_t)lt * 256;
    char* db = (char*)(dstb + (((size_t)b * 16 + lt) * NC + kc) * 16384);
    for (int p = 0; p < 2; p++) {
        __syncthreads();
        #pragma unroll
        for (int i = 0; i < 8; i++) {
            int u = t + 256 * i;
            int kr = u >> 6;
            int lc = u & 63;
            float4 v = *(const float4*)(sb + ((size_t)(p * 32 + kr)) * Ln + lc * 4);
            sm[kr][lc*4+0]=v.x; sm[kr][lc*4+1]=v.y; sm[kr][lc*4+2]=v.z; sm[kr][lc*4+3]=v.w;
        }
        __syncthreads();
        #pragma unroll
        for (int g = 0; g < 4; g++) {
            float x0[8];
            #pragma unroll
            for (int j = 0; j < 8; j++) x0[j] = sm[g*8+j][t];
            uint4 w;
            w.x = pack2h(x0[0], x0[1]);
            w.y = pack2h(x0[2], x0[3]);
            w.z = pack2h(x0[4], x0[5]);
            w.w = pack2h(x0[6], x0[7]);
            uint32_t sw = swz128((uint32_t)t * 128 + (p * 32 + g * 8) * 2);
            *(uint4*)(db + sw) = w;
        }
    }
}

// ---------------------------------------------------------------------------
// Shared GEMM mainloop (256 threads, 8 warps 64x32, 128x128 tile, 3 stages)
// ---------------------------------------------------------------------------
#define GEMM_PROLOGUE() \
    uint32_t sbase = smem_u32(smem); \
    int tid = threadIdx.x, wid = tid >> 5, lane = tid & 31; \
    int wm = wid >> 2, wn = wid & 3; \
    int sub = lane >> 3, r = lane & 7; \
    uint32_t aRow[4], aMask[4]; \
    int kaddA = (sub >> 1) * 16; \
    _Pragma("unroll") \
    for (int i = 0; i < 4; i++) { \
        uint32_t row = wm * 64 + i * 16 + (sub & 1) * 8 + r; \
        aRow[i] = row * 128; \
        aMask[i] = (aRow[i] >> 3) & 0x70; \
    } \
    uint32_t bRow[2], bMask[2]; \
    int kaddB = (sub & 1) * 16; \
    _Pragma("unroll") \
    for (int j = 0; j < 2; j++) { \
        uint32_t row = wn * 32 + j * 16 + (sub >> 1) * 8 + r; \
        bRow[j] = row * 128; \
        bMask[j] = (bRow[j] >> 3) & 0x70; \
    } \
    float acc[4][4][4]; \
    _Pragma("unroll") \
    for (int i = 0; i < 4; i++) \
        _Pragma("unroll") \
        for (int j = 0; j < 4; j++) \
            _Pragma("unroll") \
            for (int q = 0; q < 4; q++) acc[i][j][q] = 0.f;

#define GEMM_LOAD_STAGE(kc, s) do { \
    uint32_t S = sbase + (uint32_t)(s) * STG; \
    const char* ah = Abase + (size_t)(kc) * 16384; \
    const char* bh = Bbase + (size_t)(kc) * 32768; \
    _Pragma("unroll") \
    for (int q = 0; q < 4; q++) { \
        uint32_t off = (uint32_t)tid * 64 + q * 16; \
        cpasync16(S + off,         ah + off); \
        cpasync16(S + 16384 + off, bh + off); \
    } \
} while (0)

#define GEMM_MAINLOOP(NC) \
    GEMM_LOAD_STAGE(0, 0); CP_COMMIT(); \
    if ((NC) > 1) { GEMM_LOAD_STAGE(1, 1); CP_COMMIT(); } \
    int sc = 0; \
    for (int c = 0; c < (NC); c++) { \
        CP_WAIT(1); \
        __syncthreads(); \
        if (c + 2 < (NC)) { \
            int s2 = sc + 2; if (s2 >= 3) s2 -= 3; \
            GEMM_LOAD_STAGE(c + 2, s2); CP_COMMIT(); \
        } \
        uint32_t S = sbase + (uint32_t)sc * STG; \
        _Pragma("unroll") \
        for (int kk = 0; kk < 4; kk++) { \
            int kb = kk * 32; \
            uint32_t aa[16], bb[8]; \
            _Pragma("unroll") \
            for (int i = 0; i < 4; i++) \
                LDSM4(&aa[i * 4], S + aRow[i] + (uint32_t)((kaddA + kb) ^ aMask[i])); \
            _Pragma("unroll") \
            for (int j = 0; j < 2; j++) \
                LDSM4(&bb[j * 4], S + 16384 + bRow[j] + (uint32_t)((kaddB + kb) ^ bMask[j])); \
            _Pragma("unroll") \
            for (int mi = 0; mi < 4; mi++) \
                _Pragma("unroll") \
                for (int nj = 0; nj < 4; nj++) \
                    MMA16816(acc[mi][nj], &aa[mi * 4], &bb[nj * 2]); \
        } \
        sc++; if (sc == 3) sc = 0; \
    }

// ---------------------------------------------------------------------------
// Merged Q/K/V projection GEMM: grid (4, 32, 24)
// ---------------------------------------------------------------------------
__global__ __launch_bounds__(256, 2) void gemm_qkv(
    const __half* __restrict__ hf,
    const float* __restrict__ bq, const float* __restrict__ bk,
    const float* __restrict__ bv,
    __half* __restrict__ qh, __half* __restrict__ kh, __half* __restrict__ vh)
{
    extern __shared__ __align__(1024) char smem[];
    const int NC = 8;
    int mt = blockIdx.x, lt = blockIdx.y;
    int which = blockIdx.z >> 3, b = blockIdx.z & 7;

    const __half* Wc = (which == 0) ? hf + OFF_WQ : (which == 1) ? hf + OFF_WK : hf + OFF_WV;
    const float* bias = (which == 0) ? bq : (which == 1) ? bk : bv;
    const __half* Xc = (which == 0) ? hf + OFF_Z1C : hf + OFF_Z2C;
    __half* Out = (which == 0) ? qh : (which == 1) ? kh : vh;

    const char* Abase = (const char*)Wc + ((size_t)mt * NC) * 16384;
    int lt256 = lt >> 1, half = lt & 1;
    const char* Bbase = (const char*)Xc + (((size_t)b * 16 + lt256) * NC) * 32768
                        + (size_t)half * 16384;

    GEMM_PROLOGUE();
    GEMM_MAINLOOP(NC);

    int g = lane >> 2, tg = lane & 3;
    #pragma unroll
    for (int mi = 0; mi < 4; mi++) {
        #pragma unroll
        for (int h2 = 0; h2 < 2; h2++) {
            int m = mt * 128 + wm * 64 + mi * 16 + h2 * 8 + g;
            float bi = bias[m];
            size_t rowoff = ((size_t)b * 512 + m) * Ln + (size_t)lt * 128 + wn * 32;
            #pragma unroll
            for (int nj = 0; nj < 4; nj++) {
                int col = nj * 8 + 2 * tg;
                float v0 = acc[mi][nj][h2 * 2 + 0] + bi;
                float v1 = acc[mi][nj][h2 * 2 + 1] + bi;
                *(__half2*)(Out + rowoff + col) = __floats2half2_rn(v0, v1);
            }
        }
    }
}

// ---------------------------------------------------------------------------
// General GEMM. outmode 0: fp32 Out (+Res)(+ELU). outmode 1: fp16 tiled Outh.
// outmode 2: fp16 flat Outh (+Res fp32)(+ELU).
// ---------------------------------------------------------------------------
__global__ __launch_bounds__(256, 2) void gemm_wm(
    const __half* __restrict__ Wc, const float* __restrict__ bias,
    const __half* __restrict__ Xc, float* __restrict__ Out,
    __half* __restrict__ Outh,
    const float* __restrict__ Res, int M, int K, int act, int outmode)
{
    extern __shared__ __align__(1024) char smem[];
    const int NC = K >> 6;
    int mt = blockIdx.x, lt = blockIdx.y, b = blockIdx.z;

    const char* Abase = (const char*)Wc + ((size_t)mt * NC) * 16384;
    int lt256 = lt >> 1, half = lt & 1;
    const char* Bbase = (const char*)Xc + (((size_t)b * 16 + lt256) * NC) * 32768
                        + (size_t)half * 16384;

    GEMM_PROLOGUE();
    GEMM_MAINLOOP(NC);

    int g = lane >> 2, tg = lane & 3;

    if (outmode == 0) {
        #pragma unroll
        for (int mi = 0; mi < 4; mi++) {
            #pragma unroll
            for (int h2 = 0; h2 < 2; h2++) {
                int m = mt * 128 + wm * 64 + mi * 16 + h2 * 8 + g;
                float bi = bias[m];
                size_t rowoff = ((size_t)b * M + m) * Ln + (size_t)lt * 128 + wn * 32;
                #pragma unroll
                for (int nj = 0; nj < 4; nj++) {
                    int col = nj * 8 + 2 * tg;
                    float v0 = acc[mi][nj][h2 * 2 + 0] + bi;
                    float v1 = acc[mi][nj][h2 * 2 + 1] + bi;
                    if (Res) {
                        float2 r2 = *(const float2*)(Res + rowoff + col);
                        v0 += r2.x; v1 += r2.y;
                    }
                    if (act) { v0 = elu_fast(v0); v1 = elu_fast(v1); }
                    *(float2*)(Out + rowoff + col) = make_float2(v0, v1);
                }
            }
        }
    } else if (outmode == 2) {
        #pragma unroll
        for (int mi = 0; mi < 4; mi++) {
            #pragma unroll
            for (int h2 = 0; h2 < 2; h2++) {
                int m = mt * 128 + wm * 64 + mi * 16 + h2 * 8 + g;
                float bi = bias[m];
                size_t rowoff = ((size_t)b * M + m) * Ln + (size_t)lt * 128 + wn * 32;
                #pragma unroll
                for (int nj = 0; nj < 4; nj++) {
                    int col = nj * 8 + 2 * tg;
                    float v0 = acc[mi][nj][h2 * 2 + 0] + bi;
                    float v1 = acc[mi][nj][h2 * 2 + 1] + bi;
                    if (Res) {
                        float2 r2 = *(const float2*)(Res + rowoff + col);
                        v0 += r2.x; v1 += r2.y;
                    }
                    if (act) { v0 = elu_fast(v0); v1 = elu_fast(v1); }
                    *(__half2*)(Outh + rowoff + col) = __floats2half2_rn(v0, v1);
                }
            }
        }
    } else {
        __syncthreads();
        __half* smh = (__half*)smem;
        #pragma unroll
        for (int mi = 0; mi < 4; mi++) {
            #pragma unroll
            for (int h2 = 0; h2 < 2; h2++) {
                int ml = wm * 64 + mi * 16 + h2 * 8 + g;
                float bi = bias[mt * 128 + ml];
                #pragma unroll
                for (int nj = 0; nj < 4; nj++) {
                    int ll = wn * 32 + nj * 8 + 2 * tg;
                    float v0 = acc[mi][nj][h2 * 2 + 0] + bi;
                    float v1 = acc[mi][nj][h2 * 2 + 1] + bi;
                    if (act) { v0 = elu_fast(v0); v1 = elu_fast(v1); }
                    smh[(uint32_t)ll * 136 + ml]       = __float2half(v0);
                    smh[(uint32_t)(ll + 1) * 136 + ml] = __float2half(v1);
                }
            }
        }
        __syncthreads();
        int rowbase = (lt & 1) * 128;
        int NCo = M >> 6;
        #pragma unroll
        for (int kc = 0; kc < 2; kc++) {
            char* db = (char*)(Outh + (((size_t)b * 16 + lt256) * NCo + (mt * 2 + kc)) * 16384);
            #pragma unroll
            for (int it = 0; it < 4; it++) {
                int u = tid + 256 * it;
                int row = u >> 3, j = u & 7;
                uint4 w = *(uint4*)&smh[(uint32_t)row * 136 + kc * 64 + j * 8];
                *(uint4*)(db + swz128((uint32_t)(rowbase + row) * 128 + j * 16)) = w;
            }
        }
    }
}

// ---------------------------------------------------------------------------
// ctx via tensor cores (exp folded), double-buffered. grid (64, NSPLIT).
// ---------------------------------------------------------------------------
__global__ __launch_bounds__(256) void ctx_mma(
    const __half* __restrict__ kk, const __half* __restrict__ vv,
    float* __restrict__ ctxp, float* __restrict__ zp)
{
    __shared__ __align__(1024) char smem[32768];
    uint32_t sb = smem_u32(smem);
    int bh = blockIdx.x, sp = blockIdx.y;
    int tid = threadIdx.x, wid = tid >> 5, lane = tid & 31;
    const __half* kb = kk + (size_t)bh * Dh * Ln;
    const __half* vb = vv + (size_t)bh * Dh * Ln;

    int lrow = tid >> 2;
    int lu = (tid & 3) * 2;
    uint32_t sw0 = swz128((uint32_t)lrow * 128 + lu * 16);
    uint32_t sw1 = swz128((uint32_t)lrow * 128 + lu * 16 + 16);

    int mtile = wid >> 1;
    int ntile = (wid & 1) * 32;
    int sub = lane >> 3, r7 = lane & 7;
    uint32_t aRowOff = (uint32_t)(mtile * 16 + (sub & 1) * 8 + r7) * 128;
    uint32_t aMask = (aRowOff >> 3) & 0x70;
    int kaddA = (sub >> 1) * 16;
    uint32_t bRowOff[2], bMask[2];
    int kaddB = (sub & 1) * 16;
    #pragma unroll
    for (int j = 0; j < 2; j++) {
        uint32_t row = (uint32_t)(ntile + j * 16 + (sub >> 1) * 8 + r7);
        bRowOff[j] = row * 128;
        bMask[j] = (bRowOff[j] >> 3) & 0x70;
    }

    float acc[4][4];
    #pragma unroll
    for (int i = 0; i < 4; i++)
        #pragma unroll
        for (int j = 0; j < 4; j++) acc[i][j] = 0.f;
    float zacc = 0.f;

    int lbeg = sp * (Ln / NSPLIT);
    const int NCH = (Ln / NSPLIT) / 64;   // 8
    for (int ch = 0; ch < NCH; ch++) {
        int l0 = lbeg + ch * 64;
        uint32_t buf = (uint32_t)(ch & 1) * 16384;
        const __half* kr = kb + (size_t)lrow * Ln + l0 + lu * 8;
        const __half* vr = vb + (size_t)lrow * Ln + l0 + lu * 8;
        uint4 k0 = *(const uint4*)kr;
        uint4 k1 = *(const uint4*)(kr + 8);
        uint4 v0 = *(const uint4*)vr;
        uint4 v1 = *(const uint4*)(vr + 8);
        uint32_t* kw;
        kw = (uint32_t*)&k0;
        #pragma unroll
        for (int i = 0; i < 4; i++) {
            float2 f = __half22float2(*(__half2*)&kw[i]);
            f.x = __expf(f.x); f.y = __expf(f.y);
            zacc += f.x + f.y;
            kw[i] = pack2h(f.x, f.y);
        }
        kw = (uint32_t*)&k1;
        #pragma unroll
        for (int i = 0; i < 4; i++) {
            float2 f = __half22float2(*(__half2*)&kw[i]);
            f.x = __expf(f.x); f.y = __expf(f.y);
            zacc += f.x + f.y;
            kw[i] = pack2h(f.x, f.y);
        }
        *(uint4*)(smem + buf + sw0) = k0;
        *(uint4*)(smem + buf + sw1) = k1;
        *(uint4*)(smem + buf + 8192 + sw0) = v0;
        *(uint4*)(smem + buf + 8192 + sw1) = v1;
        __syncthreads();
        #pragma unroll
        for (int kk2 = 0; kk2 < 4; kk2++) {
            int kbyte = kk2 * 32;
            uint32_t aa[4], bbv[8];
            LDSM4(aa, sb + buf + aRowOff + (uint32_t)((kaddA + kbyte) ^ aMask));
            #pragma unroll
            for (int j = 0; j < 2; j++)
                LDSM4(&bbv[j * 4], sb + buf + 8192 + bRowOff[j] + (uint32_t)((kaddB + kbyte) ^ bMask[j]));
            #pragma unroll
            for (int nj = 0; nj < 4; nj++)
                MMA16816(acc[nj], aa, &bbv[nj * 2]);
        }
    }

    int g = lane >> 2, tg = lane & 3;
    float* cbase = ctxp + ((size_t)sp * 64 + bh) * 4096;
    #pragma unroll
    for (int nj = 0; nj < 4; nj++) {
        int dv = ntile + nj * 8 + 2 * tg;
        int dk0 = mtile * 16 + g;
        *(float2*)(cbase + (size_t)dk0 * 64 + dv)       = make_float2(acc[nj][0], acc[nj][1]);
        *(float2*)(cbase + (size_t)(dk0 + 8) * 64 + dv) = make_float2(acc[nj][2], acc[nj][3]);
    }
    zacc += __shfl_xor_sync(0xFFFFFFFFu, zacc, 1);
    zacc += __shfl_xor_sync(0xFFFFFFFFu, zacc, 2);
    if ((tid & 3) == 0)
        zp[((size_t)sp * 64 + bh) * 64 + lrow] = zacc;
}

// ---------------------------------------------------------------------------
// ctx_reduce: grid (4, 64); each CTA reduces a 256-float4 slice of one head.
// zinv recomputed per slice (2KB redundant reads, negligible).
// ---------------------------------------------------------------------------
__global__ __launch_bounds__(256) void ctx_reduce(
    const float* __restrict__ ctxp, const float* __restrict__ zp,
    float* __restrict__ ctxn)
{
    int quarter = blockIdx.x;
    int bh = blockIdx.y;
    __shared__ float zinv[64];
    int tid = threadIdx.x;

    if (tid < 64) {
        float zs = 0.f;
        #pragma unroll
        for (int s = 0; s < NSPLIT; s++)
            zs += zp[((size_t)s * 64 + bh) * 64 + tid];
        zinv[tid] = 1.f / zs;
    }
    __syncthreads();

    int idx = quarter * 256 + tid;         // float4 index 0..1023
    float zi = zinv[idx >> 4];
    float4 sum = make_float4(0.f, 0.f, 0.f, 0.f);
    #pragma unroll
    for (int s = 0; s < NSPLIT; s++) {
        const float4* p = (const float4*)(ctxp + ((size_t)s * 64 + bh) * 4096);
        float4 t = p[idx];
        sum.x += t.x; sum.y += t.y; sum.z += t.z; sum.w += t.w;
    }
    sum.x *= zi; sum.y *= zi; sum.z *= zi; sum.w *= zi;
    ((float4*)(ctxn + (size_t)bh * 4096))[idx] = sum;
}

// ---------------------------------------------------------------------------
// att fused: load normalized ctx once, head-softmax(q fp16) inline with
// fp16-packed weights, fp16 tiled output. grid (16, 64), 256 threads.
// ---------------------------------------------------------------------------
__global__ __launch_bounds__(256) void att_fused(
    const float* __restrict__ ctxn, const __half* __restrict__ qh,
    __half* __restrict__ attc)
{
    int bh = blockIdx.y;
    int b = bh >> 3, h = bh & 7;
    __shared__ float cs[64][64];
    int tid = threadIdx.x;

    float4* cs4 = (float4*)cs;
    const float4* p = (const float4*)(ctxn + (size_t)bh * 4096);
    #pragma unroll
    for (int r = 0; r < 4; r++) {
        int idx = tid + 256 * r;
        cs4[idx] = p[idx];
    }
    __syncthreads();

    int l = blockIdx.x * 256 + tid;
    const __half* qb = qh + (size_t)bh * Dh * Ln + l;

    uint32_t qp[32];
    {
        float qv[64];
        float mx = -1e30f;
        #pragma unroll
        for (int d = 0; d < 64; d++) {
            qv[d] = __half2float(qb[(size_t)d * Ln]);
            mx = fmaxf(mx, qv[d]);
        }
        float s = 0.f;
        #pragma unroll
        for (int d = 0; d < 64; d++) { qv[d] = __expf(qv[d] - mx); s += qv[d]; }
        float inv = 1.f / s;
        #pragma unroll
        for (int dp = 0; dp < 32; dp++)
            qp[dp] = pack2h(qv[2 * dp] * inv, qv[2 * dp + 1] * inv);
    }

    float acc[64];
    #pragma unroll
    for (int d = 0; d < 64; d++) acc[d] = 0.f;

    #pragma unroll 4
    for (int dp = 0; dp < 32; dp++) {
        float2 qq = __half22float2(*(__half2*)&qp[dp]);
        int dk0 = 2 * dp;
        #pragma unroll
        for (int j = 0; j < 16; j++) {
            float4 c0 = *(const float4*)&cs[dk0][j * 4];
            float4 c1 = *(const float4*)&cs[dk0 + 1][j * 4];
            acc[4 * j + 0] += c0.x * qq.x + c1.x * qq.y;
            acc[4 * j + 1] += c0.y * qq.x + c1.y * qq.y;
            acc[4 * j + 2] += c0.z * qq.x + c1.z * qq.y;
            acc[4 * j + 3] += c0.w * qq.x + c1.w * qq.y;
        }
    }

    char* db = (char*)(attc + (((size_t)b * 16 + blockIdx.x) * 8 + h) * 16384);
    #pragma unroll
    for (int j = 0; j < 8; j++) {
        uint4 w;
        w.x = pack2h(acc[8*j+0], acc[8*j+1]);
        w.y = pack2h(acc[8*j+2], acc[8*j+3]);
        w.z = pack2h(acc[8*j+4], acc[8*j+5]);
        w.w = pack2h(acc[8*j+6], acc[8*j+7]);
        *(uint4*)(db + swz128((uint32_t)tid * 128 + j * 16)) = w;
    }
}

// ---------------------------------------------------------------------------
// Channel LayerNorm over C=512, fp16 in -> fp32 out (single pass, reg cache)
// ---------------------------------------------------------------------------
__global__ __launch_bounds__(256) void ln_kernel(
    const __half* __restrict__ in, float* __restrict__ out,
    const float* __restrict__ g, const float* __restrict__ be)
{
    __shared__ float ss[8][32], sq[8][32], smean[32], srstd[32];
    int blk = blockIdx.x;
    int b = blk >> 7;
    int li = threadIdx.x & 31;
    int l = ((blk & 127) << 5) + li;
    int r = threadIdx.x >> 5;
    const __half* base = in + (size_t)b * Cc * Ln + l;

    float s = 0.f, s2 = 0.f;
    float x0[64];
    #pragma unroll
    for (int k2 = 0; k2 < 64; k2++) {
        int c = r * 64 + k2;
        float x = __half2float(base[(size_t)c * Ln]);
        x0[k2] = x;
        s += x; s2 += x * x;
    }
    ss[r][li] = s; sq[r][li] = s2;
    __syncthreads();
    if (r == 0) {
        float ts = ss[0][li], t2 = sq[0][li];
        #pragma unroll
        for (int rr = 1; rr < 8; rr++) { ts += ss[rr][li]; t2 += sq[rr][li]; }
        float mean = ts * (1.f / 512.f);
        float var = t2 * (1.f / 512.f) - mean * mean;
        smean[li] = mean;
        srstd[li] = rsqrtf(var + 1e-5f);
    }
    __syncthreads();
    float mean = smean[li], rstd = srstd[li];
    float* ob = out + (size_t)b * Cc * Ln + l;
    #pragma unroll
    for (int k2 = 0; k2 < 64; k2++) {
        int c = r * 64 + k2;
        ob[(size_t)c * Ln] = (x0[k2] - mean) * rstd * g[c] + be[c];
    }
}

// ---------------------------------------------------------------------------
// Channel LayerNorm, fp16 in -> fp16 tiled out
// ---------------------------------------------------------------------------
__global__ __launch_bounds__(256) void ln_h(
    const __half* __restrict__ in, __half* __restrict__ outc,
    const float* __restrict__ g, const float* __restrict__ be)
{
    __shared__ float ss[8][32], sq[8][32], smean[32], srstd[32];
    int blk = blockIdx.x;
    int b = blk >> 7;
    int li = threadIdx.x & 31;
    int l = ((blk & 127) << 5) + li;
    int r = threadIdx.x >> 5;
    const __half* base = in + (size_t)b * Cc * Ln + l;

    float s = 0.f, s2 = 0.f;
    float x0[64];
    #pragma unroll
    for (int k2 = 0; k2 < 64; k2++) {
        int c = r * 64 + k2;
        float x = __half2float(base[(size_t)c * Ln]);
        x0[k2] = x;
        s += x; s2 += x * x;
    }
    ss[r][li] = s; sq[r][li] = s2;
    __syncthreads();
    if (r == 0) {
        float ts = ss[0][li], t2 = sq[0][li];
        #pragma unroll
        for (int rr = 1; rr < 8; rr++) { ts += ss[rr][li]; t2 += sq[rr][li]; }
        float mean = ts * (1.f / 512.f);
        float var = t2 * (1.f / 512.f) - mean * mean;
        smean[li] = mean;
        srstd[li] = rsqrtf(var + 1e-5f);
    }
    __syncthreads();
    float mean = smean[li], rstd = srstd[li];

    char* db = (char*)(outc + (((size_t)b * 16 + (l >> 8)) * 8 + r) * 16384);
    uint32_t row = (uint32_t)(l & 255);
    #pragma unroll
    for (int j = 0; j < 8; j++) {
        float v[8];
        #pragma unroll
        for (int q2 = 0; q2 < 8; q2++) {
            int c = r * 64 + j * 8 + q2;
            v[q2] = (x0[j * 8 + q2] - mean) * rstd * g[c] + be[c];
        }
        uint4 w;
        w.x = pack2h(v[0], v[1]);
        w.y = pack2h(v[2], v[3]);
        w.z = pack2h(v[4], v[5]);
        w.w = pack2h(v[6], v[7]);
        *(uint4*)(db + swz128(row * 128 + j * 16)) = w;
    }
}

// ---------------------------------------------------------------------------
extern "C" void kernel_launch(void* const* d_in, const int* in_sizes, int n_in,
                              void* d_out, int out_size)
{
    const float* z1  = (const float*)d_in[0];
    const float* z2  = (const float*)d_in[1];
    const float* Wq  = (const float*)d_in[2];
    const float* bq  = (const float*)d_in[3];
    const float* Wk  = (const float*)d_in[4];
    const float* bkb = (const float*)d_in[5];
    const float* Wv  = (const float*)d_in[6];
    const float* bv  = (const float*)d_in[7];
    const float* Wr  = (const float*)d_in[8];
    const float* br  = (const float*)d_in[9];
    const float* g1  = (const float*)d_in[10];
    const float* be1 = (const float*)d_in[11];
    const float* W1  = (const float*)d_in[12];
    const float* b1  = (const float*)d_in[13];
    const float* W2  = (const float*)d_in[14];
    const float* b2  = (const float*)d_in[15];
    const float* g2  = (const float*)d_in[16];
    const float* be2 = (const float*)d_in[17];

    float* fs = nullptr;
    cudaGetSymbolAddress((void**)&fs, g_scratch);
    __half* hf = nullptr;
    cudaGetSymbolAddress((void**)&hf, g_hf);

    const size_t SZ = (size_t)Bn * Cc * Ln;   // 16777216
    __half* qh  = (__half*)(fs);
    __half* kh  = (__half*)(fs + SZ);
    __half* vh  = (__half*)(fs + 2 * SZ);
    __half* zh  = (__half*)(fs + 4 * SZ);
    __half* yh  = (__half*)(fs + 5 * SZ);
    float* ctxp = fs + 6 * SZ;                 // NSPLIT*64*64*64 floats
    float* zp   = fs + 6 * SZ + 4194304;       // NSPLIT*64*64 floats
    float* ctxn = fs + 6 * SZ + 4325376;       // 64*4096 floats

    cudaFuncSetAttribute(gemm_wm, cudaFuncAttributeMaxDynamicSharedMemorySize, GEMM_SMEM);
    cudaFuncSetAttribute(gemm_qkv, cudaFuncAttributeMaxDynamicSharedMemorySize, GEMM_SMEM);

    dim3 thr(256);
    // All conversions in one launch
    conv_all<<<dim3(16, 16, 22), thr>>>(Wq, Wk, Wv, Wr, W1, W2, z1, z2, hf);

    // Merged Q/K/V projections (all fp16 flat)
    gemm_qkv<<<dim3(4, 32, 24), thr, GEMM_SMEM>>>(hf, bq, bkb, bv, qh, kh, vh);

    // Attention core: ctx on tensor cores, widened reduce, scalar apply
    ctx_mma<<<dim3(Bn * Hh, NSPLIT), thr>>>(kh, vh, ctxp, zp);
    ctx_reduce<<<dim3(4, Bn * Hh), thr>>>(ctxp, zp, ctxn);
    att_fused<<<dim3(Ln / 256, Bn * Hh), thr>>>(ctxn, qh, hf + OFF_ATTC);

    // Reprojection + residual -> fp16 flat z
    gemm_wm<<<dim3(4, 32, 8), thr, GEMM_SMEM>>>(hf + OFF_WR, br, hf + OFF_ATTC, nullptr, zh, z1, 512, 512, 0, 2);

    // LN1 (fp16 in) -> fp16 tiled
    ln_h<<<Bn * (Ln / 32), thr>>>(zh, hf + OFF_ZC, g1, be1);

    // FFN1 -> fp16 tiled h (ELU fused), FFN2 -> fp16 flat y
    gemm_wm<<<dim3(8, 32, 8), thr, GEMM_SMEM>>>(hf + OFF_W1, b1, hf + OFF_ZC, nullptr, hf + OFF_HC, nullptr, 1024, 512, 1, 1);
    gemm_wm<<<dim3(4, 32, 8), thr, GEMM_SMEM>>>(hf + OFF_W2, b2, hf + OFF_HC, nullptr, yh, nullptr, 512, 1024, 0, 2);

    // LN2 (fp16 in) -> fp32 output
    ln_kernel<<<Bn * (Ln / 32), thr>>>(yh, (float*)d_out, g2, be2);
}